// round 14
// baseline (speedup 1.0000x reference)
#include <cuda_runtime.h>
#include <cuda_fp16.h>
#include <math.h>
#include <stdint.h>

#define BB 2
#define SS 2048
#define DMODEL 4096
#define NH 32
#define NKV 8
#define HD 128
#define MROWS (BB*SS)   // 4096
#define QSCALE 0.08838834764831845f

extern __shared__ char dyn_smem[];

// ---------------- scratch (device globals; no allocation allowed) ----------
__device__ float g_q[(size_t)MROWS * NH * HD];
__device__ float g_k[(size_t)MROWS * NKV * HD];
__device__ float g_v[(size_t)MROWS * NKV * HD];
__device__ float g_cos[MROWS * (HD/2)];
__device__ float g_sin[MROWS * (HD/2)];

// fp16 operands (weights hi only)
__device__ __half g_hid_f16[(size_t)MROWS * DMODEL];
__device__ __half g_at_f16[(size_t)MROWS * NH*HD];
__device__ __half g_wq_h[(size_t)NH*HD * DMODEL];
__device__ __half g_wk_h[(size_t)NKV*HD * DMODEL];
__device__ __half g_wv_h[(size_t)NKV*HD * DMODEL];
__device__ __half g_wo_h[(size_t)NH*HD * NH*HD];

// fp16 attention operands (post-rope, split)
__device__ __half g_qh[(size_t)MROWS * NH * HD];
__device__ __half g_ql[(size_t)MROWS * NH * HD];
__device__ __half g_kh[(size_t)MROWS * NKV * HD];
__device__ __half g_kl[(size_t)MROWS * NKV * HD];
__device__ __half g_vth[(size_t)BB * NKV * HD * SS];  // [b][kvh][d][s]

// ---------------- PTX helpers (sm_80+ base-target safe) ---------------------
__device__ __forceinline__ uint32_t smem_u32(const void* p) {
    uint32_t a;
    asm("{ .reg .u64 t; cvta.to.shared.u64 t, %1; cvt.u32.u64 %0, t; }" : "=r"(a) : "l"(p));
    return a;
}
__device__ __forceinline__ void cp16(uint32_t dst, const void* src) {
    asm volatile("cp.async.cg.shared.global [%0], [%1], 16;\n" :: "r"(dst), "l"(src));
}
__device__ __forceinline__ void cp_commit() { asm volatile("cp.async.commit_group;\n" ::: "memory"); }

__device__ __forceinline__ void ldm_x4(uint32_t* r, uint32_t addr) {
    asm volatile("ldmatrix.sync.aligned.m8n8.x4.shared.b16 {%0,%1,%2,%3}, [%4];"
        : "=r"(r[0]), "=r"(r[1]), "=r"(r[2]), "=r"(r[3]) : "r"(addr));
}
__device__ __forceinline__ void mma16816(float* d, const uint32_t* a, const uint32_t* b) {
    asm volatile("mma.sync.aligned.m16n8k16.row.col.f32.f16.f16.f32 "
        "{%0,%1,%2,%3}, {%4,%5,%6,%7}, {%8,%9}, {%0,%1,%2,%3};"
        : "+f"(d[0]), "+f"(d[1]), "+f"(d[2]), "+f"(d[3])
        : "r"(a[0]), "r"(a[1]), "r"(a[2]), "r"(a[3]), "r"(b[0]), "r"(b[1]));
}

// ---------------- conversion kernels ----------------------------------------
__global__ void tofp16(const float* __restrict__ s, __half* __restrict__ d, int n) {
    int i = blockIdx.x * blockDim.x + threadIdx.x;
    if (i < n) d[i] = __float2half(s[i]);
}

#define NW1 (NH*HD*DMODEL)
#define NW2 (NKV*HD*DMODEL)
__global__ void prep_weights(const float* __restrict__ Wq, const float* __restrict__ Wk,
                             const float* __restrict__ Wv, const float* __restrict__ Wo) {
    int i = blockIdx.x * blockDim.x + threadIdx.x;
    if (i < NW1) {
        g_wq_h[i] = __float2half(Wq[i]);
    } else if (i < NW1 + NW2) {
        int j = i - NW1;
        g_wk_h[j] = __float2half(Wk[j]);
    } else if (i < NW1 + 2*NW2) {
        int j = i - NW1 - NW2;
        g_wv_h[j] = __float2half(Wv[j]);
    } else if (i < 2*NW1 + 2*NW2) {
        int j = i - NW1 - 2*NW2;
        g_wo_h[j] = __float2half(Wo[j]);
    }
}

// ---------------------------------------------------------------------------
// Single-term fp16 GEMM core (NT). CTA 128x128, 4 warps (2x2, warp tile
// 64x64), BK=64, 3-stage cp.async, 2 CTAs/SM. 128B-row XOR swizzle both mats.
// 8 LDSM per 32 HMMA per k16 step (0.25 ldm/mma).
// ---------------------------------------------------------------------------
#define BM 128
#define BN 128
#define ST1_BYTES 32768                 // A 16K + B 16K
#define GK1_SMEM (3*ST1_BYTES + 128)    // 98432

__device__ __forceinline__ void gemm1_core(
    const __half* __restrict__ A, const __half* __restrict__ B,
    float* __restrict__ C, int bm, int bn, int N, int K) {
    uint32_t sm0 = (smem_u32(dyn_smem) + 127) & ~127u;

    int t = threadIdx.x;
    int wid = t >> 5, lane = t & 31;
    int wm = (wid >> 1) * 64;
    int wn = (wid & 1) * 64;

    float acc[4][8][4];
#pragma unroll
    for (int a = 0; a < 4; a++)
#pragma unroll
        for (int b = 0; b < 8; b++)
#pragma unroll
            for (int c = 0; c < 4; c++) acc[a][b][c] = 0.f;

    auto load_stage = [&](int s, int ck) {
        int k0 = ck * 64;
        uint32_t sb = sm0 + s * ST1_BYTES;
#pragma unroll
        for (int i = 0; i < 8; i++) {
            int idx = i * 128 + t;
            int r = idx >> 3, c = idx & 7;
            cp16(sb + r * 128 + ((c ^ (r & 7)) * 16),
                 A + (size_t)(bm + r) * K + k0 + c * 8);
        }
        uint32_t sbB = sb + 16384;
#pragma unroll
        for (int i = 0; i < 8; i++) {
            int idx = i * 128 + t;
            int r = idx >> 3, c = idx & 7;
            cp16(sbB + r * 128 + ((c ^ (r & 7)) * 16),
                 B + (size_t)(bn + r) * K + k0 + c * 8);
        }
        cp_commit();
    };

    const int NCH = K >> 6;
    load_stage(0, 0);
    load_stage(1, 1);

    int laneR = lane & 15, laneH = lane >> 4;
    uint32_t aOff[4], bOff[4];
#pragma unroll
    for (int mi = 0; mi < 4; mi++) {
        int r = wm + mi * 16 + laneR;
        aOff[mi] = sm0 + r * 128 + ((laneH ^ (r & 7)) * 16);
    }
#pragma unroll
    for (int nb = 0; nb < 4; nb++) {
        int r = wn + nb * 16 + laneR;
        bOff[nb] = sm0 + 16384 + r * 128 + ((laneH ^ (r & 7)) * 16);
    }

    for (int ch = 0; ch < NCH; ch++) {
        if (ch + 2 < NCH) {
            load_stage((ch + 2) % 3, ch + 2);
            asm volatile("cp.async.wait_group 2;\n" ::: "memory");
        } else if (ch + 1 < NCH) {
            asm volatile("cp.async.wait_group 1;\n" ::: "memory");
        } else {
            asm volatile("cp.async.wait_group 0;\n" ::: "memory");
        }
        __syncthreads();

        uint32_t soff = (uint32_t)(ch % 3) * ST1_BYTES;
#pragma unroll
        for (int kk = 0; kk < 4; kk++) {
            uint32_t kx = kk * 32;
            uint32_t ah[4][4], bh[4][4];
#pragma unroll
            for (int mi = 0; mi < 4; mi++)
                ldm_x4(ah[mi], (aOff[mi] + soff) ^ kx);
#pragma unroll
            for (int nb = 0; nb < 4; nb++)
                ldm_x4(bh[nb], (bOff[nb] + soff) ^ kx);
#pragma unroll
            for (int mi = 0; mi < 4; mi++)
#pragma unroll
                for (int nb = 0; nb < 4; nb++)
#pragma unroll
                    for (int sub = 0; sub < 2; sub++) {
                        int ni = nb * 2 + sub;
                        uint32_t fh[2] = { bh[nb][sub], bh[nb][2 + sub] };
                        mma16816(acc[mi][ni], ah[mi], fh);
                    }
        }
        __syncthreads();
    }

    int row = lane >> 2;
    int col = (lane & 3) * 2;
#pragma unroll
    for (int mi = 0; mi < 4; mi++)
#pragma unroll
        for (int ni = 0; ni < 8; ni++) {
            float* c0 = C + (size_t)(bm + wm + mi * 16 + row) * N + bn + wn + ni * 8 + col;
            c0[0] = acc[mi][ni][0];
            c0[1] = acc[mi][ni][1];
            float* c1 = c0 + 8 * (size_t)N;
            c1[0] = acc[mi][ni][2];
            c1[1] = acc[mi][ni][3];
        }
}

// fused QKV: 48 N-tiles (32 Q, 8 K, 8 V), one launch, single-term
__global__ __launch_bounds__(128, 2)
void gemm_qkv(const __half* __restrict__ A,
              const __half* __restrict__ Wqh, const __half* __restrict__ Wkh,
              const __half* __restrict__ Wvh,
              float* __restrict__ pq, float* __restrict__ pk, float* __restrict__ pv) {
    int tx = blockIdx.x;
    const __half* Bh; float* C; int N, bn;
    if (tx < 32)      { Bh = Wqh; C = pq; N = NH*HD;  bn = tx * 128; }
    else if (tx < 40) { Bh = Wkh; C = pk; N = NKV*HD; bn = (tx - 32) * 128; }
    else              { Bh = Wvh; C = pv; N = NKV*HD; bn = (tx - 40) * 128; }
    gemm1_core(A, Bh, C, blockIdx.y * BM, bn, N, DMODEL);
}

__global__ __launch_bounds__(128, 2)
void gemm_mma1(const __half* __restrict__ A, const __half* __restrict__ B,
               float* __restrict__ C, int M, int N, int K) {
    gemm1_core(A, B, C, blockIdx.y * BM, blockIdx.x * BN, N, K);
}

// ---------------- RoPE table: fp64 reduce, fp32 sincos -----------------------
__global__ void rope_table(const int* __restrict__ pos) {
    int idx = blockIdx.x * blockDim.x + threadIdx.x;
    if (idx >= MROWS * 64) return;
    int i   = idx & 63;
    int row = idx >> 6;
    double inv = exp(-(double)(2 * i) / 128.0 * log(10000.0));
    double ang = (double)pos[row] * inv;
    float a = (float)fmod(ang, 6.283185307179586476925287);
    g_cos[idx] = __cosf(a);
    g_sin[idx] = __sinf(a);
}

// ---------------- fused RoPE + fp16 hi/lo split (q and k in one pass) --------
__global__ void rope_split_qk() {
    int idx = blockIdx.x * blockDim.x + threadIdx.x;
    const int total = MROWS * (NH + NKV) * 64;
    if (idx >= total) return;
    int i    = idx & 63;
    int head = (idx >> 6) % (NH + NKV);
    int row  = idx / (64 * (NH + NKV));
    float c = g_cos[row * 64 + i];
    float s = g_sin[row * 64 + i];
    if (head < NH) {
        size_t o = (size_t)row * NH * HD + head * HD;
        float x1 = g_q[o + i], x2 = g_q[o + i + 64];
        float y1 = (x1 * c - x2 * s) * QSCALE;
        float y2 = (x2 * c + x1 * s) * QSCALE;
        __half h1 = __float2half(y1), h2 = __float2half(y2);
        g_qh[o + i] = h1;      g_ql[o + i]      = __float2half(y1 - __half2float(h1));
        g_qh[o + i + 64] = h2; g_ql[o + i + 64] = __float2half(y2 - __half2float(h2));
    } else {
        size_t o = (size_t)row * NKV * HD + (head - NH) * HD;
        float x1 = g_k[o + i], x2 = g_k[o + i + 64];
        float y1 = x1 * c - x2 * s;
        float y2 = x2 * c + x1 * s;
        __half h1 = __float2half(y1), h2 = __float2half(y2);
        g_kh[o + i] = h1;      g_kl[o + i]      = __float2half(y1 - __half2float(h1));
        g_kh[o + i + 64] = h2; g_kl[o + i + 64] = __float2half(y2 - __half2float(h2));
    }
}

// ---------------- V transpose: g_v -> Vt[b][kvh][d][s] fp16 (hi only) --------
__global__ __launch_bounds__(256) void split_vt() {
    __shared__ float sv[64][129];
    int blk = blockIdx.x;
    int st  = blk & 31;
    int kvh = (blk >> 5) & 7;
    int b   = blk >> 8;
    int tid = threadIdx.x;
#pragma unroll
    for (int it = 0; it < 32; it++) {
        int idx = it * 256 + tid;
        int r = idx >> 7, c = idx & 127;
        sv[r][c] = g_v[(size_t)(b * SS + st * 64 + r) * (NKV * HD) + kvh * HD + c];
    }
    __syncthreads();
    int d = tid >> 1, j = tid & 1;
    __half hbuf[32];
#pragma unroll
    for (int q = 0; q < 32; q++)
        hbuf[q] = __float2half(sv[j * 32 + q][d]);
    size_t base = ((size_t)(b * NKV + kvh) * HD + d) * SS + st * 64 + j * 32;
    uint4* dh = (uint4*)(g_vth + base);
#pragma unroll
    for (int q = 0; q < 4; q++)
        dh[q] = ((uint4*)hbuf)[q];
}

// ---------------------------------------------------------------------------
// HMMA flash attention: Br=128 (8 warps), Bc=64; QK 3-term, PV 2-term (P split).
// ---------------------------------------------------------------------------
#define SQH 0
#define SQL 32768
#define SKH 65536
#define SKL 81920
#define SVH 98304
#define FL_SMEM 114688

__global__ __launch_bounds__(256) void flash_mma(
    const __half* __restrict__ Qh_g, const __half* __restrict__ Ql_g,
    const __half* __restrict__ Kh_g, const __half* __restrict__ Kl_g,
    const __half* __restrict__ Vth_g,
    __half* __restrict__ out) {
    uint32_t s0 = smem_u32(dyn_smem);

    int qt = blockIdx.x, h = blockIdx.y, b = blockIdx.z;
    int kvh = h >> 2;
    int t = threadIdx.x, wid = t >> 5, lane = t & 31;
    int laneR = lane & 15, laneH = lane >> 4;
    int wm = wid * 16;

#pragma unroll
    for (int i = 0; i < 8; i++) {
        int idx = i * 256 + t;
        int r = idx >> 4, c = idx & 15;
        uint32_t d = r * 256 + ((c ^ (r & 7)) * 16);
        size_t g = ((size_t)(b * SS + qt * 128 + r)) * (NH * HD) + h * HD + c * 8;
        cp16(s0 + SQH + d, Qh_g + g);
        cp16(s0 + SQL + d, Ql_g + g);
    }
    auto loadKV = [&](int kt) {
#pragma unroll
        for (int i = 0; i < 4; i++) {
            int idx = i * 256 + t;
            int r = idx >> 4, c = idx & 15;
            uint32_t d = r * 256 + ((c ^ (r & 7)) * 16);
            size_t g = ((size_t)(b * SS + kt * 64 + r)) * (NKV * HD) + kvh * HD + c * 8;
            cp16(s0 + SKH + d, Kh_g + g);
            cp16(s0 + SKL + d, Kl_g + g);
        }
#pragma unroll
        for (int i = 0; i < 4; i++) {
            int idx = i * 256 + t;
            int r = idx >> 3, c = idx & 7;
            uint32_t d = r * 128 + ((c ^ (r & 7)) * 16);
            size_t g = ((size_t)((b * NKV + kvh) * HD + r)) * SS + kt * 64 + c * 8;
            cp16(s0 + SVH + d, Vth_g + g);
        }
    };
    loadKV(0);
    cp_commit();

    float o_[16][4];
#pragma unroll
    for (int n = 0; n < 16; n++)
#pragma unroll
        for (int c = 0; c < 4; c++) o_[n][c] = 0.f;
    float m0 = -1e30f, m1 = -1e30f, l0 = 0.f, l1 = 0.f;
    int r0 = lane >> 2;
    int qrow0 = qt * 128 + wm + r0;
    int qrow1 = qrow0 + 8;
    const int KTMAX = 2 * qt + 1;

    for (int kt = 0; kt <= KTMAX; kt++) {
        asm volatile("cp.async.wait_group 0;\n" ::: "memory");
        __syncthreads();

        float s[8][4];
#pragma unroll
        for (int j = 0; j < 8; j++)
#pragma unroll
            for (int c = 0; c < 4; c++) s[j][c] = 0.f;

#pragma unroll
        for (int kk = 0; kk < 8; kk++) {
            uint32_t qa[4], qb[4];
            {
                int r = wm + laneR;
                uint32_t ph = (uint32_t)(((kk * 2 + laneH) ^ (r & 7)) * 16);
                ldm_x4(qa, s0 + SQH + r * 256 + ph);
                ldm_x4(qb, s0 + SQL + r * 256 + ph);
            }
#pragma unroll
            for (int jj = 0; jj < 4; jj++) {
                uint32_t kh_[4], kl_[4];
                int r = jj * 16 + laneR;
                uint32_t ph = (uint32_t)(((kk * 2 + laneH) ^ (r & 7)) * 16);
                ldm_x4(kh_, s0 + SKH + r * 256 + ph);
                ldm_x4(kl_, s0 + SKL + r * 256 + ph);
#pragma unroll
                for (int sub = 0; sub < 2; sub++) {
                    int j = jj * 2 + sub;
                    uint32_t fh[2] = { kh_[sub], kh_[2 + sub] };
                    uint32_t fl[2] = { kl_[sub], kl_[2 + sub] };
                    mma16816(s[j], qa, fh);
                    mma16816(s[j], qa, fl);
                    mma16816(s[j], qb, fh);
                }
            }
        }

        if (kt * 64 + 63 > qrow0) {
#pragma unroll
            for (int j = 0; j < 8; j++) {
                int cb = kt * 64 + j * 8 + (lane & 3) * 2;
                if (cb     > qrow0) s[j][0] = -1e30f;
                if (cb + 1 > qrow0) s[j][1] = -1e30f;
                if (cb     > qrow1) s[j][2] = -1e30f;
                if (cb + 1 > qrow1) s[j][3] = -1e30f;
            }
        }

        float rm0 = -1e30f, rm1 = -1e30f;
#pragma unroll
        for (int j = 0; j < 8; j++) {
            rm0 = fmaxf(rm0, fmaxf(s[j][0], s[j][1]));
            rm1 = fmaxf(rm1, fmaxf(s[j][2], s[j][3]));
        }
        rm0 = fmaxf(rm0, __shfl_xor_sync(0xffffffffu, rm0, 1));
        rm0 = fmaxf(rm0, __shfl_xor_sync(0xffffffffu, rm0, 2));
        rm1 = fmaxf(rm1, __shfl_xor_sync(0xffffffffu, rm1, 1));
        rm1 = fmaxf(rm1, __shfl_xor_sync(0xffffffffu, rm1, 2));
        float mn0 = fmaxf(m0, rm0), mn1 = fmaxf(m1, rm1);
        float a0 = __expf(m0 - mn0), a1 = __expf(m1 - mn1);
        l0 *= a0; l1 *= a1;
#pragma unroll
        for (int n = 0; n < 16; n++) {
            o_[n][0] *= a0; o_[n][1] *= a0;
            o_[n][2] *= a1; o_[n][3] *= a1;
        }
        m0 = mn0; m1 = mn1;

        uint32_t ph0[8], ph1[8], pl0[8], pl1[8];
        float sum0 = 0.f, sum1 = 0.f;
#pragma unroll
        for (int j = 0; j < 8; j++) {
            float e0 = __expf(s[j][0] - mn0), e1 = __expf(s[j][1] - mn0);
            float e2 = __expf(s[j][2] - mn1), e3 = __expf(s[j][3] - mn1);
            sum0 += e0 + e1; sum1 += e2 + e3;
            __half2 hh0 = __floats2half2_rn(e0, e1);
            __half2 hh1 = __floats2half2_rn(e2, e3);
            ph0[j] = *(uint32_t*)&hh0;
            ph1[j] = *(uint32_t*)&hh1;
            __half2 dd0 = __floats2half2_rn(e0 - __low2float(hh0), e1 - __high2float(hh0));
            __half2 dd1 = __floats2half2_rn(e2 - __low2float(hh1), e3 - __high2float(hh1));
            pl0[j] = *(uint32_t*)&dd0;
            pl1[j] = *(uint32_t*)&dd1;
        }
        sum0 += __shfl_xor_sync(0xffffffffu, sum0, 1);
        sum0 += __shfl_xor_sync(0xffffffffu, sum0, 2);
        sum1 += __shfl_xor_sync(0xffffffffu, sum1, 1);
        sum1 += __shfl_xor_sync(0xffffffffu, sum1, 2);
        l0 += sum0; l1 += sum1;

#pragma unroll
        for (int tt = 0; tt < 4; tt++) {
            uint32_t pa[4] = { ph0[2*tt], ph1[2*tt], ph0[2*tt+1], ph1[2*tt+1] };
            uint32_t pb[4] = { pl0[2*tt], pl1[2*tt], pl0[2*tt+1], pl1[2*tt+1] };
#pragma unroll
            for (int dg = 0; dg < 8; dg++) {
                uint32_t vh_[4];
                int r = dg * 16 + laneR;
                uint32_t ph = (uint32_t)(((tt * 2 + laneH) ^ (r & 7)) * 16);
                ldm_x4(vh_, s0 + SVH + r * 128 + ph);
#pragma unroll
                for (int sub = 0; sub < 2; sub++) {
                    int n = dg * 2 + sub;
                    uint32_t fh[2] = { vh_[sub], vh_[2 + sub] };
                    mma16816(o_[n], pa, fh);
                    mma16816(o_[n], pb, fh);
                }
            }
        }

        __syncthreads();
        if (kt + 1 <= KTMAX) {
            loadKV(kt + 1);
            cp_commit();
        }
    }

    float il0 = 1.f / l0, il1 = 1.f / l1;
    size_t ob0 = (size_t)(b * SS + qrow0) * (NH * HD) + h * HD + (lane & 3) * 2;
    size_t ob1 = (size_t)(b * SS + qrow1) * (NH * HD) + h * HD + (lane & 3) * 2;
#pragma unroll
    for (int n = 0; n < 16; n++) {
        __half2 w0 = __floats2half2_rn(o_[n][0] * il0, o_[n][1] * il0);
        __half2 w1 = __floats2half2_rn(o_[n][2] * il1, o_[n][3] * il1);
        *(__half2*)(out + ob0 + n * 8) = w0;
        *(__half2*)(out + ob1 + n * 8) = w1;
    }
}

// ---------------------------------------------------------------------------
extern "C" void kernel_launch(void* const* d_in, const int* in_sizes, int n_in,
                              void* d_out, int out_size) {
    const float* hid = (const float*)d_in[0];
    const int*   pos = (const int*)d_in[1];
    const float* Wq  = (const float*)d_in[2];
    const float* Wk  = (const float*)d_in[3];
    const float* Wv  = (const float*)d_in[4];
    const float* Wo  = (const float*)d_in[5];
    float* out = (float*)d_out;

    float *pq, *pk, *pv;
    cudaGetSymbolAddress((void**)&pq, g_q);
    cudaGetSymbolAddress((void**)&pk, g_k);
    cudaGetSymbolAddress((void**)&pv, g_v);
    __half *hf, *af, *qh, *kh, *vh, *oh;
    __half *fqh, *fql, *fkh, *fkl, *fvh;
    cudaGetSymbolAddress((void**)&hf, g_hid_f16);
    cudaGetSymbolAddress((void**)&af, g_at_f16);
    cudaGetSymbolAddress((void**)&qh, g_wq_h);
    cudaGetSymbolAddress((void**)&kh, g_wk_h);
    cudaGetSymbolAddress((void**)&vh, g_wv_h);
    cudaGetSymbolAddress((void**)&oh, g_wo_h);
    cudaGetSymbolAddress((void**)&fqh, g_qh);   cudaGetSymbolAddress((void**)&fql, g_ql);
    cudaGetSymbolAddress((void**)&fkh, g_kh);   cudaGetSymbolAddress((void**)&fkl, g_kl);
    cudaGetSymbolAddress((void**)&fvh, g_vth);

    const int nHid = MROWS * DMODEL;
    const int nPrep = 2 * NW1 + 2 * NW2;
    tofp16<<<(nHid + 255) / 256, 256>>>(hid, hf, nHid);
    prep_weights<<<(nPrep + 255) / 256, 256>>>(Wq, Wk, Wv, Wo);
    rope_table<<<(MROWS*64 + 255)/256, 256>>>(pos);

    cudaFuncSetAttribute(gemm_qkv, cudaFuncAttributeMaxDynamicSharedMemorySize, GK1_SMEM);
    cudaFuncSetAttribute(gemm_mma1, cudaFuncAttributeMaxDynamicSharedMemorySize, GK1_SMEM);

    gemm_qkv<<<dim3(48, MROWS/BM), 128, GK1_SMEM>>>(hf, qh, kh, vh, pq, pk, pv);

    rope_split_qk<<<(MROWS*(NH+NKV)*64 + 255)/256, 256>>>();
    split_vt<<<BB*NKV*32, 256>>>();

    cudaFuncSetAttribute(flash_mma, cudaFuncAttributeMaxDynamicSharedMemorySize, FL_SMEM);
    flash_mma<<<dim3(SS/128, NH, BB), 256, FL_SMEM>>>(fqh, fql, fkh, fkl, fvh, af);

    gemm_mma1<<<dim3(NH*HD/BN, MROWS/BM), 128, GK1_SMEM>>>(af, oh, out, MROWS, NH*HD, NH*HD);
}

// round 15
// speedup vs baseline: 1.0611x; 1.0611x over previous
#include <cuda_runtime.h>
#include <cuda_fp16.h>
#include <math.h>
#include <stdint.h>

#define BB 2
#define SS 2048
#define DMODEL 4096
#define NH 32
#define NKV 8
#define HD 128
#define MROWS (BB*SS)   // 4096
#define QSCALE 0.08838834764831845f

extern __shared__ char dyn_smem[];

// ---------------- scratch (device globals; no allocation allowed) ----------
__device__ float g_q[(size_t)MROWS * NH * HD];
__device__ float g_k[(size_t)MROWS * NKV * HD];
__device__ float g_v[(size_t)MROWS * NKV * HD];
__device__ float g_cos[MROWS * (HD/2)];
__device__ float g_sin[MROWS * (HD/2)];

// fp16 operands (weights hi only)
__device__ __half g_hid_f16[(size_t)MROWS * DMODEL];
__device__ __half g_at_f16[(size_t)MROWS * NH*HD];
__device__ __half g_wq_h[(size_t)NH*HD * DMODEL];
__device__ __half g_wk_h[(size_t)NKV*HD * DMODEL];
__device__ __half g_wv_h[(size_t)NKV*HD * DMODEL];
__device__ __half g_wo_h[(size_t)NH*HD * NH*HD];

// fp16 attention operands (post-rope, split)
__device__ __half g_qh[(size_t)MROWS * NH * HD];
__device__ __half g_ql[(size_t)MROWS * NH * HD];
__device__ __half g_kh[(size_t)MROWS * NKV * HD];
__device__ __half g_kl[(size_t)MROWS * NKV * HD];
__device__ __half g_vth[(size_t)BB * NKV * HD * SS];  // [b][kvh][d][s]

// ---------------- PTX helpers (sm_80+ base-target safe) ---------------------
__device__ __forceinline__ uint32_t smem_u32(const void* p) {
    uint32_t a;
    asm("{ .reg .u64 t; cvta.to.shared.u64 t, %1; cvt.u32.u64 %0, t; }" : "=r"(a) : "l"(p));
    return a;
}
__device__ __forceinline__ void cp16(uint32_t dst, const void* src) {
    asm volatile("cp.async.cg.shared.global [%0], [%1], 16;\n" :: "r"(dst), "l"(src));
}
__device__ __forceinline__ void cp_commit() { asm volatile("cp.async.commit_group;\n" ::: "memory"); }

__device__ __forceinline__ void ldm_x4(uint32_t* r, uint32_t addr) {
    asm volatile("ldmatrix.sync.aligned.m8n8.x4.shared.b16 {%0,%1,%2,%3}, [%4];"
        : "=r"(r[0]), "=r"(r[1]), "=r"(r[2]), "=r"(r[3]) : "r"(addr));
}
__device__ __forceinline__ void mma16816(float* d, const uint32_t* a, const uint32_t* b) {
    asm volatile("mma.sync.aligned.m16n8k16.row.col.f32.f16.f16.f32 "
        "{%0,%1,%2,%3}, {%4,%5,%6,%7}, {%8,%9}, {%0,%1,%2,%3};"
        : "+f"(d[0]), "+f"(d[1]), "+f"(d[2]), "+f"(d[3])
        : "r"(a[0]), "r"(a[1]), "r"(a[2]), "r"(a[3]), "r"(b[0]), "r"(b[1]));
}

// ---------------- fused prep: hid fp16, 4 weights fp16, rope table ----------
#define NW1 (NH*HD*DMODEL)      // 16777216
#define NW2 (NKV*HD*DMODEL)     // 4194304
#define NHID (MROWS*DMODEL)     // 16777216
#define NTAB (MROWS*64)         // 262144
#define NPREP (NHID + 2*NW1 + 2*NW2 + NTAB)

__global__ void prep_all(const float* __restrict__ hid,
                         const float* __restrict__ Wq, const float* __restrict__ Wk,
                         const float* __restrict__ Wv, const float* __restrict__ Wo,
                         const int* __restrict__ pos) {
    int i = blockIdx.x * blockDim.x + threadIdx.x;
    if (i < NHID) {
        g_hid_f16[i] = __float2half(hid[i]);
    } else if (i < NHID + NW1) {
        int j = i - NHID;
        g_wq_h[j] = __float2half(Wq[j]);
    } else if (i < NHID + NW1 + NW2) {
        int j = i - NHID - NW1;
        g_wk_h[j] = __float2half(Wk[j]);
    } else if (i < NHID + NW1 + 2*NW2) {
        int j = i - NHID - NW1 - NW2;
        g_wv_h[j] = __float2half(Wv[j]);
    } else if (i < NHID + 2*NW1 + 2*NW2) {
        int j = i - NHID - NW1 - 2*NW2;
        g_wo_h[j] = __float2half(Wo[j]);
    } else if (i < NPREP) {
        int j = i - NHID - 2*NW1 - 2*NW2;
        int fi  = j & 63;
        int row = j >> 6;
        double inv = exp(-(double)(2 * fi) / 128.0 * log(10000.0));
        double ang = (double)pos[row] * inv;
        float a = (float)fmod(ang, 6.283185307179586476925287);
        g_cos[j] = __cosf(a);
        g_sin[j] = __sinf(a);
    }
}

// ---------------------------------------------------------------------------
// Single-term fp16 GEMM core (NT). CTA 128x128, 8 warps (2x4, warp tile
// 64x32), BK=64, 3-stage cp.async, 2 CTAs/SM. 128B-row XOR swizzle both mats.
// ---------------------------------------------------------------------------
#define BM 128
#define BN 128
#define ST1_BYTES 32768                 // A 16K + B 16K
#define GK1_SMEM (3*ST1_BYTES + 128)    // 98432

__device__ __forceinline__ void gemm1_core(
    const __half* __restrict__ A, const __half* __restrict__ B,
    float* __restrict__ C, int bm, int bn, int N, int K) {
    uint32_t sm0 = (smem_u32(dyn_smem) + 127) & ~127u;

    int t = threadIdx.x;
    int wid = t >> 5, lane = t & 31;
    int wm = (wid >> 2) * 64;
    int wn = (wid & 3) * 32;

    float acc[4][4][4];
#pragma unroll
    for (int a = 0; a < 4; a++)
#pragma unroll
        for (int b = 0; b < 4; b++)
#pragma unroll
            for (int c = 0; c < 4; c++) acc[a][b][c] = 0.f;

    auto load_stage = [&](int s, int ck) {
        int k0 = ck * 64;
        uint32_t sb = sm0 + s * ST1_BYTES;
#pragma unroll
        for (int i = 0; i < 4; i++) {
            int idx = i * 256 + t;
            int r = idx >> 3, c = idx & 7;
            cp16(sb + r * 128 + ((c ^ (r & 7)) * 16),
                 A + (size_t)(bm + r) * K + k0 + c * 8);
        }
        uint32_t sbB = sb + 16384;
#pragma unroll
        for (int i = 0; i < 4; i++) {
            int idx = i * 256 + t;
            int r = idx >> 3, c = idx & 7;
            cp16(sbB + r * 128 + ((c ^ (r & 7)) * 16),
                 B + (size_t)(bn + r) * K + k0 + c * 8);
        }
        cp_commit();
    };

    const int NCH = K >> 6;
    load_stage(0, 0);
    load_stage(1, 1);

    int laneR = lane & 15, laneH = lane >> 4;
    uint32_t aOff[4], bOff[2];
#pragma unroll
    for (int mi = 0; mi < 4; mi++) {
        int r = wm + mi * 16 + laneR;
        aOff[mi] = sm0 + r * 128 + ((laneH ^ (r & 7)) * 16);
    }
#pragma unroll
    for (int nb = 0; nb < 2; nb++) {
        int r = wn + nb * 16 + laneR;
        bOff[nb] = sm0 + 16384 + r * 128 + ((laneH ^ (r & 7)) * 16);
    }

    for (int ch = 0; ch < NCH; ch++) {
        if (ch + 2 < NCH) {
            load_stage((ch + 2) % 3, ch + 2);
            asm volatile("cp.async.wait_group 2;\n" ::: "memory");
        } else if (ch + 1 < NCH) {
            asm volatile("cp.async.wait_group 1;\n" ::: "memory");
        } else {
            asm volatile("cp.async.wait_group 0;\n" ::: "memory");
        }
        __syncthreads();

        uint32_t soff = (uint32_t)(ch % 3) * ST1_BYTES;
#pragma unroll
        for (int kk = 0; kk < 4; kk++) {
            uint32_t kx = kk * 32;
            uint32_t ah[4][4];
#pragma unroll
            for (int mi = 0; mi < 4; mi++)
                ldm_x4(ah[mi], (aOff[mi] + soff) ^ kx);
#pragma unroll
            for (int nb = 0; nb < 2; nb++) {
                uint32_t bh[4];
                ldm_x4(bh, (bOff[nb] + soff) ^ kx);
#pragma unroll
                for (int mi = 0; mi < 4; mi++)
#pragma unroll
                    for (int sub = 0; sub < 2; sub++) {
                        int ni = nb * 2 + sub;
                        uint32_t fh[2] = { bh[sub], bh[2 + sub] };
                        mma16816(acc[mi][ni], ah[mi], fh);
                    }
            }
        }
        __syncthreads();
    }

    int row = lane >> 2;
    int col = (lane & 3) * 2;
#pragma unroll
    for (int mi = 0; mi < 4; mi++)
#pragma unroll
        for (int ni = 0; ni < 4; ni++) {
            float* c0 = C + (size_t)(bm + wm + mi * 16 + row) * N + bn + wn + ni * 8 + col;
            c0[0] = acc[mi][ni][0];
            c0[1] = acc[mi][ni][1];
            float* c1 = c0 + 8 * (size_t)N;
            c1[0] = acc[mi][ni][2];
            c1[1] = acc[mi][ni][3];
        }
}

// fused QKV: 48 N-tiles (32 Q, 8 K, 8 V), one launch, single-term
__global__ __launch_bounds__(256, 2)
void gemm_qkv(const __half* __restrict__ A,
              const __half* __restrict__ Wqh, const __half* __restrict__ Wkh,
              const __half* __restrict__ Wvh,
              float* __restrict__ pq, float* __restrict__ pk, float* __restrict__ pv) {
    int tx = blockIdx.x;
    const __half* Bh; float* C; int N, bn;
    if (tx < 32)      { Bh = Wqh; C = pq; N = NH*HD;  bn = tx * 128; }
    else if (tx < 40) { Bh = Wkh; C = pk; N = NKV*HD; bn = (tx - 32) * 128; }
    else              { Bh = Wvh; C = pv; N = NKV*HD; bn = (tx - 40) * 128; }
    gemm1_core(A, Bh, C, blockIdx.y * BM, bn, N, DMODEL);
}

__global__ __launch_bounds__(256, 2)
void gemm_mma1(const __half* __restrict__ A, const __half* __restrict__ B,
               float* __restrict__ C, int M, int N, int K) {
    gemm1_core(A, B, C, blockIdx.y * BM, blockIdx.x * BN, N, K);
}

// ---------------- fused RoPE + fp16 hi/lo split (q and k in one pass) --------
__global__ void rope_split_qk() {
    int idx = blockIdx.x * blockDim.x + threadIdx.x;
    const int total = MROWS * (NH + NKV) * 64;
    if (idx >= total) return;
    int i    = idx & 63;
    int head = (idx >> 6) % (NH + NKV);
    int row  = idx / (64 * (NH + NKV));
    float c = g_cos[row * 64 + i];
    float s = g_sin[row * 64 + i];
    if (head < NH) {
        size_t o = (size_t)row * NH * HD + head * HD;
        float x1 = g_q[o + i], x2 = g_q[o + i + 64];
        float y1 = (x1 * c - x2 * s) * QSCALE;
        float y2 = (x2 * c + x1 * s) * QSCALE;
        __half h1 = __float2half(y1), h2 = __float2half(y2);
        g_qh[o + i] = h1;      g_ql[o + i]      = __float2half(y1 - __half2float(h1));
        g_qh[o + i + 64] = h2; g_ql[o + i + 64] = __float2half(y2 - __half2float(h2));
    } else {
        size_t o = (size_t)row * NKV * HD + (head - NH) * HD;
        float x1 = g_k[o + i], x2 = g_k[o + i + 64];
        float y1 = x1 * c - x2 * s;
        float y2 = x2 * c + x1 * s;
        __half h1 = __float2half(y1), h2 = __float2half(y2);
        g_kh[o + i] = h1;      g_kl[o + i]      = __float2half(y1 - __half2float(h1));
        g_kh[o + i + 64] = h2; g_kl[o + i + 64] = __float2half(y2 - __half2float(h2));
    }
}

// ---------------- V transpose: g_v -> Vt[b][kvh][d][s] fp16 (hi only) --------
__global__ __launch_bounds__(256) void split_vt() {
    __shared__ float sv[64][129];
    int blk = blockIdx.x;
    int st  = blk & 31;
    int kvh = (blk >> 5) & 7;
    int b   = blk >> 8;
    int tid = threadIdx.x;
#pragma unroll
    for (int it = 0; it < 32; it++) {
        int idx = it * 256 + tid;
        int r = idx >> 7, c = idx & 127;
        sv[r][c] = g_v[(size_t)(b * SS + st * 64 + r) * (NKV * HD) + kvh * HD + c];
    }
    __syncthreads();
    int d = tid >> 1, j = tid & 1;
    __half hbuf[32];
#pragma unroll
    for (int q = 0; q < 32; q++)
        hbuf[q] = __float2half(sv[j * 32 + q][d]);
    size_t base = ((size_t)(b * NKV + kvh) * HD + d) * SS + st * 64 + j * 32;
    uint4* dh = (uint4*)(g_vth + base);
#pragma unroll
    for (int q = 0; q < 4; q++)
        dh[q] = ((uint4*)hbuf)[q];
}

// ---------------------------------------------------------------------------
// HMMA flash attention: Br=128 (8 warps), Bc=64; QK 3-term, PV 2-term (P split).
// Double-buffered KV stages: Q 64KB + 2 x (K 32KB + V 16KB) = 160KB smem.
// kt+1 load issued BEFORE computing kt -> loads overlap compute.
// ---------------------------------------------------------------------------
#define SQH 0
#define SQL 32768
#define SKV 65536
#define KVSTG 49152     // Kh 16K | Kl 16K | Vh 16K
#define FL_SMEM (65536 + 2*KVSTG)   // 163840

__global__ __launch_bounds__(256) void flash_mma(
    const __half* __restrict__ Qh_g, const __half* __restrict__ Ql_g,
    const __half* __restrict__ Kh_g, const __half* __restrict__ Kl_g,
    const __half* __restrict__ Vth_g,
    __half* __restrict__ out) {
    uint32_t s0 = smem_u32(dyn_smem);

    int qt = blockIdx.x, h = blockIdx.y, b = blockIdx.z;
    int kvh = h >> 2;
    int t = threadIdx.x, wid = t >> 5, lane = t & 31;
    int laneR = lane & 15, laneH = lane >> 4;
    int wm = wid * 16;

    // Q tile (group 0, with KV stage 0)
#pragma unroll
    for (int i = 0; i < 8; i++) {
        int idx = i * 256 + t;
        int r = idx >> 4, c = idx & 15;
        uint32_t d = r * 256 + ((c ^ (r & 7)) * 16);
        size_t g = ((size_t)(b * SS + qt * 128 + r)) * (NH * HD) + h * HD + c * 8;
        cp16(s0 + SQH + d, Qh_g + g);
        cp16(s0 + SQL + d, Ql_g + g);
    }
    auto loadKV = [&](int kt, int st) {
        uint32_t base = s0 + SKV + (uint32_t)st * KVSTG;
#pragma unroll
        for (int i = 0; i < 4; i++) {
            int idx = i * 256 + t;
            int r = idx >> 4, c = idx & 15;
            uint32_t d = r * 256 + ((c ^ (r & 7)) * 16);
            size_t g = ((size_t)(b * SS + kt * 64 + r)) * (NKV * HD) + kvh * HD + c * 8;
            cp16(base + d, Kh_g + g);          // Kh rows interleave into 16K+16K
        }
        // note: Kh/Kl each 64 rows x 256B = 16KB; store Kl after Kh
        uint32_t baseL = base + 16384;
#pragma unroll
        for (int i = 0; i < 4; i++) {
            int idx = i * 256 + t;
            int r = idx >> 4, c = idx & 15;
            uint32_t d = r * 256 + ((c ^ (r & 7)) * 16);
            size_t g = ((size_t)(b * SS + kt * 64 + r)) * (NKV * HD) + kvh * HD + c * 8;
            cp16(baseL + d, Kl_g + g);
        }
        uint32_t baseV = base + 32768;
#pragma unroll
        for (int i = 0; i < 4; i++) {
            int idx = i * 256 + t;
            int r = idx >> 3, c = idx & 7;
            uint32_t d = r * 128 + ((c ^ (r & 7)) * 16);
            size_t g = ((size_t)((b * NKV + kvh) * HD + r)) * SS + kt * 64 + c * 8;
            cp16(baseV + d, Vth_g + g);
        }
        cp_commit();
    };
    loadKV(0, 0);

    float o_[16][4];
#pragma unroll
    for (int n = 0; n < 16; n++)
#pragma unroll
        for (int c = 0; c < 4; c++) o_[n][c] = 0.f;
    float m0 = -1e30f, m1 = -1e30f, l0 = 0.f, l1 = 0.f;
    int r0 = lane >> 2;
    int qrow0 = qt * 128 + wm + r0;
    int qrow1 = qrow0 + 8;
    const int KTMAX = 2 * qt + 1;

    for (int kt = 0; kt <= KTMAX; kt++) {
        // prefetch next KV tile into the other stage BEFORE computing this one
        if (kt < KTMAX) {
            loadKV(kt + 1, (kt + 1) & 1);
            asm volatile("cp.async.wait_group 1;\n" ::: "memory");
        } else {
            asm volatile("cp.async.wait_group 0;\n" ::: "memory");
        }
        __syncthreads();

        uint32_t kvb  = s0 + SKV + (uint32_t)(kt & 1) * KVSTG;
        uint32_t kvbl = kvb + 16384;
        uint32_t kvbv = kvb + 32768;

        float s[8][4];
#pragma unroll
        for (int j = 0; j < 8; j++)
#pragma unroll
            for (int c = 0; c < 4; c++) s[j][c] = 0.f;

#pragma unroll
        for (int kk = 0; kk < 8; kk++) {
            uint32_t qa[4], qb[4];
            {
                int r = wm + laneR;
                uint32_t ph = (uint32_t)(((kk * 2 + laneH) ^ (r & 7)) * 16);
                ldm_x4(qa, s0 + SQH + r * 256 + ph);
                ldm_x4(qb, s0 + SQL + r * 256 + ph);
            }
#pragma unroll
            for (int jj = 0; jj < 4; jj++) {
                uint32_t kh_[4], kl_[4];
                int r = jj * 16 + laneR;
                uint32_t ph = (uint32_t)(((kk * 2 + laneH) ^ (r & 7)) * 16);
                ldm_x4(kh_, kvb  + r * 256 + ph);
                ldm_x4(kl_, kvbl + r * 256 + ph);
#pragma unroll
                for (int sub = 0; sub < 2; sub++) {
                    int j = jj * 2 + sub;
                    uint32_t fh[2] = { kh_[sub], kh_[2 + sub] };
                    uint32_t fl[2] = { kl_[sub], kl_[2 + sub] };
                    mma16816(s[j], qa, fh);
                    mma16816(s[j], qa, fl);
                    mma16816(s[j], qb, fh);
                }
            }
        }

        if (kt * 64 + 63 > qrow0) {
#pragma unroll
            for (int j = 0; j < 8; j++) {
                int cb = kt * 64 + j * 8 + (lane & 3) * 2;
                if (cb     > qrow0) s[j][0] = -1e30f;
                if (cb + 1 > qrow0) s[j][1] = -1e30f;
                if (cb     > qrow1) s[j][2] = -1e30f;
                if (cb + 1 > qrow1) s[j][3] = -1e30f;
            }
        }

        float rm0 = -1e30f, rm1 = -1e30f;
#pragma unroll
        for (int j = 0; j < 8; j++) {
            rm0 = fmaxf(rm0, fmaxf(s[j][0], s[j][1]));
            rm1 = fmaxf(rm1, fmaxf(s[j][2], s[j][3]));
        }
        rm0 = fmaxf(rm0, __shfl_xor_sync(0xffffffffu, rm0, 1));
        rm0 = fmaxf(rm0, __shfl_xor_sync(0xffffffffu, rm0, 2));
        rm1 = fmaxf(rm1, __shfl_xor_sync(0xffffffffu, rm1, 1));
        rm1 = fmaxf(rm1, __shfl_xor_sync(0xffffffffu, rm1, 2));
        float mn0 = fmaxf(m0, rm0), mn1 = fmaxf(m1, rm1);
        float a0 = __expf(m0 - mn0), a1 = __expf(m1 - mn1);
        l0 *= a0; l1 *= a1;
#pragma unroll
        for (int n = 0; n < 16; n++) {
            o_[n][0] *= a0; o_[n][1] *= a0;
            o_[n][2] *= a1; o_[n][3] *= a1;
        }
        m0 = mn0; m1 = mn1;

        uint32_t ph0[8], ph1[8], pl0[8], pl1[8];
        float sum0 = 0.f, sum1 = 0.f;
#pragma unroll
        for (int j = 0; j < 8; j++) {
            float e0 = __expf(s[j][0] - mn0), e1 = __expf(s[j][1] - mn0);
            float e2 = __expf(s[j][2] - mn1), e3 = __expf(s[j][3] - mn1);
            sum0 += e0 + e1; sum1 += e2 + e3;
            __half2 hh0 = __floats2half2_rn(e0, e1);
            __half2 hh1 = __floats2half2_rn(e2, e3);
            ph0[j] = *(uint32_t*)&hh0;
            ph1[j] = *(uint32_t*)&hh1;
            __half2 dd0 = __floats2half2_rn(e0 - __low2float(hh0), e1 - __high2float(hh0));
            __half2 dd1 = __floats2half2_rn(e2 - __low2float(hh1), e3 - __high2float(hh1));
            pl0[j] = *(uint32_t*)&dd0;
            pl1[j] = *(uint32_t*)&dd1;
        }
        sum0 += __shfl_xor_sync(0xffffffffu, sum0, 1);
        sum0 += __shfl_xor_sync(0xffffffffu, sum0, 2);
        sum1 += __shfl_xor_sync(0xffffffffu, sum1, 1);
        sum1 += __shfl_xor_sync(0xffffffffu, sum1, 2);
        l0 += sum0; l1 += sum1;

#pragma unroll
        for (int tt = 0; tt < 4; tt++) {
            uint32_t pa[4] = { ph0[2*tt], ph1[2*tt], ph0[2*tt+1], ph1[2*tt+1] };
            uint32_t pb[4] = { pl0[2*tt], pl1[2*tt], pl0[2*tt+1], pl1[2*tt+1] };
#pragma unroll
            for (int dg = 0; dg < 8; dg++) {
                uint32_t vh_[4];
                int r = dg * 16 + laneR;
                uint32_t ph = (uint32_t)(((tt * 2 + laneH) ^ (r & 7)) * 16);
                ldm_x4(vh_, kvbv + r * 128 + ph);
#pragma unroll
                for (int sub = 0; sub < 2; sub++) {
                    int n = dg * 2 + sub;
                    uint32_t fh[2] = { vh_[sub], vh_[2 + sub] };
                    mma16816(o_[n], pa, fh);
                    mma16816(o_[n], pb, fh);
                }
            }
        }

        __syncthreads();   // all reads of stage (kt&1) done before its reuse at kt+2
    }

    float il0 = 1.f / l0, il1 = 1.f / l1;
    size_t ob0 = (size_t)(b * SS + qrow0) * (NH * HD) + h * HD + (lane & 3) * 2;
    size_t ob1 = (size_t)(b * SS + qrow1) * (NH * HD) + h * HD + (lane & 3) * 2;
#pragma unroll
    for (int n = 0; n < 16; n++) {
        __half2 w0 = __floats2half2_rn(o_[n][0] * il0, o_[n][1] * il0);
        __half2 w1 = __floats2half2_rn(o_[n][2] * il1, o_[n][3] * il1);
        *(__half2*)(out + ob0 + n * 8) = w0;
        *(__half2*)(out + ob1 + n * 8) = w1;
    }
}

// ---------------------------------------------------------------------------
extern "C" void kernel_launch(void* const* d_in, const int* in_sizes, int n_in,
                              void* d_out, int out_size) {
    const float* hid = (const float*)d_in[0];
    const int*   pos = (const int*)d_in[1];
    const float* Wq  = (const float*)d_in[2];
    const float* Wk  = (const float*)d_in[3];
    const float* Wv  = (const float*)d_in[4];
    const float* Wo  = (const float*)d_in[5];
    float* out = (float*)d_out;

    float *pq, *pk, *pv;
    cudaGetSymbolAddress((void**)&pq, g_q);
    cudaGetSymbolAddress((void**)&pk, g_k);
    cudaGetSymbolAddress((void**)&pv, g_v);
    __half *hf, *af, *qh, *kh, *vh, *oh;
    __half *fqh, *fql, *fkh, *fkl, *fvh;
    cudaGetSymbolAddress((void**)&hf, g_hid_f16);
    cudaGetSymbolAddress((void**)&af, g_at_f16);
    cudaGetSymbolAddress((void**)&qh, g_wq_h);
    cudaGetSymbolAddress((void**)&kh, g_wk_h);
    cudaGetSymbolAddress((void**)&vh, g_wv_h);
    cudaGetSymbolAddress((void**)&oh, g_wo_h);
    cudaGetSymbolAddress((void**)&fqh, g_qh);   cudaGetSymbolAddress((void**)&fql, g_ql);
    cudaGetSymbolAddress((void**)&fkh, g_kh);   cudaGetSymbolAddress((void**)&fkl, g_kl);
    cudaGetSymbolAddress((void**)&fvh, g_vth);

    prep_all<<<(NPREP + 255) / 256, 256>>>(hid, Wq, Wk, Wv, Wo, pos);

    cudaFuncSetAttribute(gemm_qkv, cudaFuncAttributeMaxDynamicSharedMemorySize, GK1_SMEM);
    cudaFuncSetAttribute(gemm_mma1, cudaFuncAttributeMaxDynamicSharedMemorySize, GK1_SMEM);

    gemm_qkv<<<dim3(48, MROWS/BM), 256, GK1_SMEM>>>(hf, qh, kh, vh, pq, pk, pv);

    rope_split_qk<<<(MROWS*(NH+NKV)*64 + 255)/256, 256>>>();
    split_vt<<<BB*NKV*32, 256>>>();

    cudaFuncSetAttribute(flash_mma, cudaFuncAttributeMaxDynamicSharedMemorySize, FL_SMEM);
    flash_mma<<<dim3(SS/128, NH, BB), 256, FL_SMEM>>>(fqh, fql, fkh, fkl, fvh, af);

    gemm_mma1<<<dim3(NH*HD/BN, MROWS/BM), 256, GK1_SMEM>>>(af, oh, out, MROWS, NH*HD, NH*HD);
}

// round 16
// speedup vs baseline: 1.1029x; 1.0394x over previous
#include <cuda_runtime.h>
#include <cuda_fp16.h>
#include <math.h>
#include <stdint.h>

#define BB 2
#define SS 2048
#define DMODEL 4096
#define NH 32
#define NKV 8
#define HD 128
#define MROWS (BB*SS)   // 4096
#define QSCALE 0.08838834764831845f

extern __shared__ char dyn_smem[];

// ---------------- scratch (device globals; no allocation allowed) ----------
__device__ float g_q[(size_t)MROWS * NH * HD];
__device__ float g_k[(size_t)MROWS * NKV * HD];
__device__ float g_v[(size_t)MROWS * NKV * HD];
__device__ float g_cos[MROWS * (HD/2)];
__device__ float g_sin[MROWS * (HD/2)];

// fp16 operands (weights hi only)
__device__ __half g_hid_f16[(size_t)MROWS * DMODEL];
__device__ __half g_at_f16[(size_t)MROWS * NH*HD];
__device__ __half g_wq_h[(size_t)NH*HD * DMODEL];
__device__ __half g_wk_h[(size_t)NKV*HD * DMODEL];
__device__ __half g_wv_h[(size_t)NKV*HD * DMODEL];
__device__ __half g_wo_h[(size_t)NH*HD * NH*HD];

// fp16 attention operands (post-rope, split)
__device__ __half g_qh[(size_t)MROWS * NH * HD];
__device__ __half g_ql[(size_t)MROWS * NH * HD];
__device__ __half g_kh[(size_t)MROWS * NKV * HD];
__device__ __half g_kl[(size_t)MROWS * NKV * HD];
__device__ __half g_vth[(size_t)BB * NKV * HD * SS];  // [b][kvh][d][s]

// ---------------- PTX helpers (sm_80+ base-target safe) ---------------------
__device__ __forceinline__ uint32_t smem_u32(const void* p) {
    uint32_t a;
    asm("{ .reg .u64 t; cvta.to.shared.u64 t, %1; cvt.u32.u64 %0, t; }" : "=r"(a) : "l"(p));
    return a;
}
__device__ __forceinline__ void cp16(uint32_t dst, const void* src) {
    asm volatile("cp.async.cg.shared.global [%0], [%1], 16;\n" :: "r"(dst), "l"(src));
}
__device__ __forceinline__ void cp_commit() { asm volatile("cp.async.commit_group;\n" ::: "memory"); }

__device__ __forceinline__ void ldm_x4(uint32_t* r, uint32_t addr) {
    asm volatile("ldmatrix.sync.aligned.m8n8.x4.shared.b16 {%0,%1,%2,%3}, [%4];"
        : "=r"(r[0]), "=r"(r[1]), "=r"(r[2]), "=r"(r[3]) : "r"(addr));
}
__device__ __forceinline__ void mma16816(float* d, const uint32_t* a, const uint32_t* b) {
    asm volatile("mma.sync.aligned.m16n8k16.row.col.f32.f16.f16.f32 "
        "{%0,%1,%2,%3}, {%4,%5,%6,%7}, {%8,%9}, {%0,%1,%2,%3};"
        : "+f"(d[0]), "+f"(d[1]), "+f"(d[2]), "+f"(d[3])
        : "r"(a[0]), "r"(a[1]), "r"(a[2]), "r"(a[3]), "r"(b[0]), "r"(b[1]));
}

// ---------------- fused prep (vectorized x4): fp32 -> fp16 + rope table ------
#define NW1 (NH*HD*DMODEL)      // 16777216
#define NW2 (NKV*HD*DMODEL)     // 4194304
#define NHID (MROWS*DMODEL)     // 16777216
#define NTAB (MROWS*64)         // 262144
// all region sizes divisible by 4
#define V_HID (NHID/4)
#define V_W1  (NW1/4)
#define V_W2  (NW2/4)
#define V_TAB (NTAB/4)
#define NPREP4 (V_HID + 2*V_W1 + 2*V_W2 + V_TAB)

__device__ __forceinline__ void cvt4(const float* __restrict__ src,
                                     __half* __restrict__ dst, int j4) {
    float4 f = ((const float4*)src)[j4];
    __half2 h0 = __floats2half2_rn(f.x, f.y);
    __half2 h1 = __floats2half2_rn(f.z, f.w);
    ((__half2*)dst)[j4 * 2 + 0] = h0;
    ((__half2*)dst)[j4 * 2 + 1] = h1;
}

__global__ void prep_all(const float* __restrict__ hid,
                         const float* __restrict__ Wq, const float* __restrict__ Wk,
                         const float* __restrict__ Wv, const float* __restrict__ Wo,
                         const int* __restrict__ pos) {
    int i = blockIdx.x * blockDim.x + threadIdx.x;
    if (i < V_HID) {
        cvt4(hid, g_hid_f16, i);
    } else if (i < V_HID + V_W1) {
        cvt4(Wq, g_wq_h, i - V_HID);
    } else if (i < V_HID + V_W1 + V_W2) {
        cvt4(Wk, g_wk_h, i - V_HID - V_W1);
    } else if (i < V_HID + V_W1 + 2*V_W2) {
        cvt4(Wv, g_wv_h, i - V_HID - V_W1 - V_W2);
    } else if (i < V_HID + 2*V_W1 + 2*V_W2) {
        cvt4(Wo, g_wo_h, i - V_HID - V_W1 - 2*V_W2);
    } else if (i < NPREP4) {
        int j4 = i - V_HID - 2*V_W1 - 2*V_W2;
        int j = j4 * 4;
        int row = j >> 6;
        int p = pos[row];
#pragma unroll
        for (int u = 0; u < 4; u++) {
            int fi = (j + u) & 63;
            double inv = exp(-(double)(2 * fi) / 128.0 * log(10000.0));
            double ang = (double)p * inv;
            float a = (float)fmod(ang, 6.283185307179586476925287);
            g_cos[j + u] = __cosf(a);
            g_sin[j + u] = __sinf(a);
        }
    }
}

// ---------------------------------------------------------------------------
// Single-term fp16 GEMM core (NT). CTA 128x128, 8 warps (2x4, warp tile
// 64x32), BK=64, 3-stage cp.async, 2 CTAs/SM. 128B-row XOR swizzle both mats.
// ---------------------------------------------------------------------------
#define BM 128
#define BN 128
#define ST1_BYTES 32768                 // A 16K + B 16K
#define GK1_SMEM (3*ST1_BYTES + 128)    // 98432

__device__ __forceinline__ void gemm1_core(
    const __half* __restrict__ A, const __half* __restrict__ B,
    float* __restrict__ C, int bm, int bn, int N, int K) {
    uint32_t sm0 = (smem_u32(dyn_smem) + 127) & ~127u;

    int t = threadIdx.x;
    int wid = t >> 5, lane = t & 31;
    int wm = (wid >> 2) * 64;
    int wn = (wid & 3) * 32;

    float acc[4][4][4];
#pragma unroll
    for (int a = 0; a < 4; a++)
#pragma unroll
        for (int b = 0; b < 4; b++)
#pragma unroll
            for (int c = 0; c < 4; c++) acc[a][b][c] = 0.f;

    auto load_stage = [&](int s, int ck) {
        int k0 = ck * 64;
        uint32_t sb = sm0 + s * ST1_BYTES;
#pragma unroll
        for (int i = 0; i < 4; i++) {
            int idx = i * 256 + t;
            int r = idx >> 3, c = idx & 7;
            cp16(sb + r * 128 + ((c ^ (r & 7)) * 16),
                 A + (size_t)(bm + r) * K + k0 + c * 8);
        }
        uint32_t sbB = sb + 16384;
#pragma unroll
        for (int i = 0; i < 4; i++) {
            int idx = i * 256 + t;
            int r = idx >> 3, c = idx & 7;
            cp16(sbB + r * 128 + ((c ^ (r & 7)) * 16),
                 B + (size_t)(bn + r) * K + k0 + c * 8);
        }
        cp_commit();
    };

    const int NCH = K >> 6;
    load_stage(0, 0);
    load_stage(1, 1);

    int laneR = lane & 15, laneH = lane >> 4;
    uint32_t aOff[4], bOff[2];
#pragma unroll
    for (int mi = 0; mi < 4; mi++) {
        int r = wm + mi * 16 + laneR;
        aOff[mi] = sm0 + r * 128 + ((laneH ^ (r & 7)) * 16);
    }
#pragma unroll
    for (int nb = 0; nb < 2; nb++) {
        int r = wn + nb * 16 + laneR;
        bOff[nb] = sm0 + 16384 + r * 128 + ((laneH ^ (r & 7)) * 16);
    }

    for (int ch = 0; ch < NCH; ch++) {
        if (ch + 2 < NCH) {
            load_stage((ch + 2) % 3, ch + 2);
            asm volatile("cp.async.wait_group 2;\n" ::: "memory");
        } else if (ch + 1 < NCH) {
            asm volatile("cp.async.wait_group 1;\n" ::: "memory");
        } else {
            asm volatile("cp.async.wait_group 0;\n" ::: "memory");
        }
        __syncthreads();

        uint32_t soff = (uint32_t)(ch % 3) * ST1_BYTES;
#pragma unroll
        for (int kk = 0; kk < 4; kk++) {
            uint32_t kx = kk * 32;
            uint32_t ah[4][4];
#pragma unroll
            for (int mi = 0; mi < 4; mi++)
                ldm_x4(ah[mi], (aOff[mi] + soff) ^ kx);
#pragma unroll
            for (int nb = 0; nb < 2; nb++) {
                uint32_t bh[4];
                ldm_x4(bh, (bOff[nb] + soff) ^ kx);
#pragma unroll
                for (int mi = 0; mi < 4; mi++)
#pragma unroll
                    for (int sub = 0; sub < 2; sub++) {
                        int ni = nb * 2 + sub;
                        uint32_t fh[2] = { bh[sub], bh[2 + sub] };
                        mma16816(acc[mi][ni], ah[mi], fh);
                    }
            }
        }
        __syncthreads();
    }

    int row = lane >> 2;
    int col = (lane & 3) * 2;
#pragma unroll
    for (int mi = 0; mi < 4; mi++)
#pragma unroll
        for (int ni = 0; ni < 4; ni++) {
            float* c0 = C + (size_t)(bm + wm + mi * 16 + row) * N + bn + wn + ni * 8 + col;
            c0[0] = acc[mi][ni][0];
            c0[1] = acc[mi][ni][1];
            float* c1 = c0 + 8 * (size_t)N;
            c1[0] = acc[mi][ni][2];
            c1[1] = acc[mi][ni][3];
        }
}

// fused QKV: 48 N-tiles (32 Q, 8 K, 8 V), one launch, single-term
__global__ __launch_bounds__(256, 2)
void gemm_qkv(const __half* __restrict__ A,
              const __half* __restrict__ Wqh, const __half* __restrict__ Wkh,
              const __half* __restrict__ Wvh,
              float* __restrict__ pq, float* __restrict__ pk, float* __restrict__ pv) {
    int tx = blockIdx.x;
    const __half* Bh; float* C; int N, bn;
    if (tx < 32)      { Bh = Wqh; C = pq; N = NH*HD;  bn = tx * 128; }
    else if (tx < 40) { Bh = Wkh; C = pk; N = NKV*HD; bn = (tx - 32) * 128; }
    else              { Bh = Wvh; C = pv; N = NKV*HD; bn = (tx - 40) * 128; }
    gemm1_core(A, Bh, C, blockIdx.y * BM, bn, N, DMODEL);
}

__global__ __launch_bounds__(256, 2)
void gemm_mma1(const __half* __restrict__ A, const __half* __restrict__ B,
               float* __restrict__ C, int M, int N, int K) {
    gemm1_core(A, B, C, blockIdx.y * BM, blockIdx.x * BN, N, K);
}

// ---------------- fused RoPE + fp16 hi/lo split (vectorized x2) --------------
// thread handles i,i+1 (even i) and partner dims i+64,i+65 of one head-row.
__global__ void rope_split_qk() {
    int idx = blockIdx.x * blockDim.x + threadIdx.x;
    const int total = MROWS * (NH + NKV) * 32;
    if (idx >= total) return;
    int i2   = idx & 31;                 // pair index 0..31
    int i    = i2 * 2;
    int head = (idx >> 5) % (NH + NKV);
    int row  = idx / (32 * (NH + NKV));
    float2 cc = *(const float2*)&g_cos[row * 64 + i];
    float2 ss = *(const float2*)&g_sin[row * 64 + i];
    if (head < NH) {
        size_t o = (size_t)row * NH * HD + head * HD;
        float2 x1 = *(const float2*)&g_q[o + i];
        float2 x2 = *(const float2*)&g_q[o + i + 64];
        float y1a = (x1.x * cc.x - x2.x * ss.x) * QSCALE;
        float y1b = (x1.y * cc.y - x2.y * ss.y) * QSCALE;
        float y2a = (x2.x * cc.x + x1.x * ss.x) * QSCALE;
        float y2b = (x2.y * cc.y + x1.y * ss.y) * QSCALE;
        __half2 h1 = __floats2half2_rn(y1a, y1b);
        __half2 h2 = __floats2half2_rn(y2a, y2b);
        *(__half2*)&g_qh[o + i]      = h1;
        *(__half2*)&g_qh[o + i + 64] = h2;
        *(__half2*)&g_ql[o + i]      = __floats2half2_rn(y1a - __low2float(h1), y1b - __high2float(h1));
        *(__half2*)&g_ql[o + i + 64] = __floats2half2_rn(y2a - __low2float(h2), y2b - __high2float(h2));
    } else {
        size_t o = (size_t)row * NKV * HD + (head - NH) * HD;
        float2 x1 = *(const float2*)&g_k[o + i];
        float2 x2 = *(const float2*)&g_k[o + i + 64];
        float y1a = x1.x * cc.x - x2.x * ss.x;
        float y1b = x1.y * cc.y - x2.y * ss.y;
        float y2a = x2.x * cc.x + x1.x * ss.x;
        float y2b = x2.y * cc.y + x1.y * ss.y;
        __half2 h1 = __floats2half2_rn(y1a, y1b);
        __half2 h2 = __floats2half2_rn(y2a, y2b);
        *(__half2*)&g_kh[o + i]      = h1;
        *(__half2*)&g_kh[o + i + 64] = h2;
        *(__half2*)&g_kl[o + i]      = __floats2half2_rn(y1a - __low2float(h1), y1b - __high2float(h1));
        *(__half2*)&g_kl[o + i + 64] = __floats2half2_rn(y2a - __low2float(h2), y2b - __high2float(h2));
    }
}

// ---------------- V transpose: g_v -> Vt[b][kvh][d][s] fp16 (hi only) --------
__global__ __launch_bounds__(256) void split_vt() {
    __shared__ float sv[64][129];
    int blk = blockIdx.x;
    int st  = blk & 31;
    int kvh = (blk >> 5) & 7;
    int b   = blk >> 8;
    int tid = threadIdx.x;
#pragma unroll
    for (int it = 0; it < 32; it++) {
        int idx = it * 256 + tid;
        int r = idx >> 7, c = idx & 127;
        sv[r][c] = g_v[(size_t)(b * SS + st * 64 + r) * (NKV * HD) + kvh * HD + c];
    }
    __syncthreads();
    int d = tid >> 1, j = tid & 1;
    __half hbuf[32];
#pragma unroll
    for (int q = 0; q < 32; q++)
        hbuf[q] = __float2half(sv[j * 32 + q][d]);
    size_t base = ((size_t)(b * NKV + kvh) * HD + d) * SS + st * 64 + j * 32;
    uint4* dh = (uint4*)(g_vth + base);
#pragma unroll
    for (int q = 0; q < 4; q++)
        dh[q] = ((uint4*)hbuf)[q];
}

// ---------------------------------------------------------------------------
// HMMA flash attention: Br=128 (8 warps), Bc=64; QK 3-term, PV 2-term (P split).
// Double-buffered KV stages; prefetch kt+1 before computing kt.
// ---------------------------------------------------------------------------
#define SQH 0
#define SQL 32768
#define SKV 65536
#define KVSTG 49152
#define FL_SMEM (65536 + 2*KVSTG)   // 163840

__global__ __launch_bounds__(256) void flash_mma(
    const __half* __restrict__ Qh_g, const __half* __restrict__ Ql_g,
    const __half* __restrict__ Kh_g, const __half* __restrict__ Kl_g,
    const __half* __restrict__ Vth_g,
    __half* __restrict__ out) {
    uint32_t s0 = smem_u32(dyn_smem);

    int qt = blockIdx.x, h = blockIdx.y, b = blockIdx.z;
    int kvh = h >> 2;
    int t = threadIdx.x, wid = t >> 5, lane = t & 31;
    int laneR = lane & 15, laneH = lane >> 4;
    int wm = wid * 16;

#pragma unroll
    for (int i = 0; i < 8; i++) {
        int idx = i * 256 + t;
        int r = idx >> 4, c = idx & 15;
        uint32_t d = r * 256 + ((c ^ (r & 7)) * 16);
        size_t g = ((size_t)(b * SS + qt * 128 + r)) * (NH * HD) + h * HD + c * 8;
        cp16(s0 + SQH + d, Qh_g + g);
        cp16(s0 + SQL + d, Ql_g + g);
    }
    auto loadKV = [&](int kt, int st) {
        uint32_t base = s0 + SKV + (uint32_t)st * KVSTG;
#pragma unroll
        for (int i = 0; i < 4; i++) {
            int idx = i * 256 + t;
            int r = idx >> 4, c = idx & 15;
            uint32_t d = r * 256 + ((c ^ (r & 7)) * 16);
            size_t g = ((size_t)(b * SS + kt * 64 + r)) * (NKV * HD) + kvh * HD + c * 8;
            cp16(base + d, Kh_g + g);
        }
        uint32_t baseL = base + 16384;
#pragma unroll
        for (int i = 0; i < 4; i++) {
            int idx = i * 256 + t;
            int r = idx >> 4, c = idx & 15;
            uint32_t d = r * 256 + ((c ^ (r & 7)) * 16);
            size_t g = ((size_t)(b * SS + kt * 64 + r)) * (NKV * HD) + kvh * HD + c * 8;
            cp16(baseL + d, Kl_g + g);
        }
        uint32_t baseV = base + 32768;
#pragma unroll
        for (int i = 0; i < 4; i++) {
            int idx = i * 256 + t;
            int r = idx >> 3, c = idx & 7;
            uint32_t d = r * 128 + ((c ^ (r & 7)) * 16);
            size_t g = ((size_t)((b * NKV + kvh) * HD + r)) * SS + kt * 64 + c * 8;
            cp16(baseV + d, Vth_g + g);
        }
        cp_commit();
    };
    loadKV(0, 0);

    float o_[16][4];
#pragma unroll
    for (int n = 0; n < 16; n++)
#pragma unroll
        for (int c = 0; c < 4; c++) o_[n][c] = 0.f;
    float m0 = -1e30f, m1 = -1e30f, l0 = 0.f, l1 = 0.f;
    int r0 = lane >> 2;
    int qrow0 = qt * 128 + wm + r0;
    int qrow1 = qrow0 + 8;
    const int KTMAX = 2 * qt + 1;

    for (int kt = 0; kt <= KTMAX; kt++) {
        if (kt < KTMAX) {
            loadKV(kt + 1, (kt + 1) & 1);
            asm volatile("cp.async.wait_group 1;\n" ::: "memory");
        } else {
            asm volatile("cp.async.wait_group 0;\n" ::: "memory");
        }
        __syncthreads();

        uint32_t kvb  = s0 + SKV + (uint32_t)(kt & 1) * KVSTG;
        uint32_t kvbl = kvb + 16384;
        uint32_t kvbv = kvb + 32768;

        float s[8][4];
#pragma unroll
        for (int j = 0; j < 8; j++)
#pragma unroll
            for (int c = 0; c < 4; c++) s[j][c] = 0.f;

#pragma unroll
        for (int kk = 0; kk < 8; kk++) {
            uint32_t qa[4], qb[4];
            {
                int r = wm + laneR;
                uint32_t ph = (uint32_t)(((kk * 2 + laneH) ^ (r & 7)) * 16);
                ldm_x4(qa, s0 + SQH + r * 256 + ph);
                ldm_x4(qb, s0 + SQL + r * 256 + ph);
            }
#pragma unroll
            for (int jj = 0; jj < 4; jj++) {
                uint32_t kh_[4], kl_[4];
                int r = jj * 16 + laneR;
                uint32_t ph = (uint32_t)(((kk * 2 + laneH) ^ (r & 7)) * 16);
                ldm_x4(kh_, kvb  + r * 256 + ph);
                ldm_x4(kl_, kvbl + r * 256 + ph);
#pragma unroll
                for (int sub = 0; sub < 2; sub++) {
                    int j = jj * 2 + sub;
                    uint32_t fh[2] = { kh_[sub], kh_[2 + sub] };
                    uint32_t fl[2] = { kl_[sub], kl_[2 + sub] };
                    mma16816(s[j], qa, fh);
                    mma16816(s[j], qa, fl);
                    mma16816(s[j], qb, fh);
                }
            }
        }

        if (kt * 64 + 63 > qrow0) {
#pragma unroll
            for (int j = 0; j < 8; j++) {
                int cb = kt * 64 + j * 8 + (lane & 3) * 2;
                if (cb     > qrow0) s[j][0] = -1e30f;
                if (cb + 1 > qrow0) s[j][1] = -1e30f;
                if (cb     > qrow1) s[j][2] = -1e30f;
                if (cb + 1 > qrow1) s[j][3] = -1e30f;
            }
        }

        float rm0 = -1e30f, rm1 = -1e30f;
#pragma unroll
        for (int j = 0; j < 8; j++) {
            rm0 = fmaxf(rm0, fmaxf(s[j][0], s[j][1]));
            rm1 = fmaxf(rm1, fmaxf(s[j][2], s[j][3]));
        }
        rm0 = fmaxf(rm0, __shfl_xor_sync(0xffffffffu, rm0, 1));
        rm0 = fmaxf(rm0, __shfl_xor_sync(0xffffffffu, rm0, 2));
        rm1 = fmaxf(rm1, __shfl_xor_sync(0xffffffffu, rm1, 1));
        rm1 = fmaxf(rm1, __shfl_xor_sync(0xffffffffu, rm1, 2));
        float mn0 = fmaxf(m0, rm0), mn1 = fmaxf(m1, rm1);
        float a0 = __expf(m0 - mn0), a1 = __expf(m1 - mn1);
        l0 *= a0; l1 *= a1;
#pragma unroll
        for (int n = 0; n < 16; n++) {
            o_[n][0] *= a0; o_[n][1] *= a0;
            o_[n][2] *= a1; o_[n][3] *= a1;
        }
        m0 = mn0; m1 = mn1;

        uint32_t ph0[8], ph1[8], pl0[8], pl1[8];
        float sum0 = 0.f, sum1 = 0.f;
#pragma unroll
        for (int j = 0; j < 8; j++) {
            float e0 = __expf(s[j][0] - mn0), e1 = __expf(s[j][1] - mn0);
            float e2 = __expf(s[j][2] - mn1), e3 = __expf(s[j][3] - mn1);
            sum0 += e0 + e1; sum1 += e2 + e3;
            __half2 hh0 = __floats2half2_rn(e0, e1);
            __half2 hh1 = __floats2half2_rn(e2, e3);
            ph0[j] = *(uint32_t*)&hh0;
            ph1[j] = *(uint32_t*)&hh1;
            __half2 dd0 = __floats2half2_rn(e0 - __low2float(hh0), e1 - __high2float(hh0));
            __half2 dd1 = __floats2half2_rn(e2 - __low2float(hh1), e3 - __high2float(hh1));
            pl0[j] = *(uint32_t*)&dd0;
            pl1[j] = *(uint32_t*)&dd1;
        }
        sum0 += __shfl_xor_sync(0xffffffffu, sum0, 1);
        sum0 += __shfl_xor_sync(0xffffffffu, sum0, 2);
        sum1 += __shfl_xor_sync(0xffffffffu, sum1, 1);
        sum1 += __shfl_xor_sync(0xffffffffu, sum1, 2);
        l0 += sum0; l1 += sum1;

#pragma unroll
        for (int tt = 0; tt < 4; tt++) {
            uint32_t pa[4] = { ph0[2*tt], ph1[2*tt], ph0[2*tt+1], ph1[2*tt+1] };
            uint32_t pb[4] = { pl0[2*tt], pl1[2*tt], pl0[2*tt+1], pl1[2*tt+1] };
#pragma unroll
            for (int dg = 0; dg < 8; dg++) {
                uint32_t vh_[4];
                int r = dg * 16 + laneR;
                uint32_t ph = (uint32_t)(((tt * 2 + laneH) ^ (r & 7)) * 16);
                ldm_x4(vh_, kvbv + r * 128 + ph);
#pragma unroll
                for (int sub = 0; sub < 2; sub++) {
                    int n = dg * 2 + sub;
                    uint32_t fh[2] = { vh_[sub], vh_[2 + sub] };
                    mma16816(o_[n], pa, fh);
                    mma16816(o_[n], pb, fh);
                }
            }
        }

        __syncthreads();
    }

    float il0 = 1.f / l0, il1 = 1.f / l1;
    size_t ob0 = (size_t)(b * SS + qrow0) * (NH * HD) + h * HD + (lane & 3) * 2;
    size_t ob1 = (size_t)(b * SS + qrow1) * (NH * HD) + h * HD + (lane & 3) * 2;
#pragma unroll
    for (int n = 0; n < 16; n++) {
        __half2 w0 = __floats2half2_rn(o_[n][0] * il0, o_[n][1] * il0);
        __half2 w1 = __floats2half2_rn(o_[n][2] * il1, o_[n][3] * il1);
        *(__half2*)(out + ob0 + n * 8) = w0;
        *(__half2*)(out + ob1 + n * 8) = w1;
    }
}

// ---------------------------------------------------------------------------
extern "C" void kernel_launch(void* const* d_in, const int* in_sizes, int n_in,
                              void* d_out, int out_size) {
    const float* hid = (const float*)d_in[0];
    const int*   pos = (const int*)d_in[1];
    const float* Wq  = (const float*)d_in[2];
    const float* Wk  = (const float*)d_in[3];
    const float* Wv  = (const float*)d_in[4];
    const float* Wo  = (const float*)d_in[5];
    float* out = (float*)d_out;

    float *pq, *pk, *pv;
    cudaGetSymbolAddress((void**)&pq, g_q);
    cudaGetSymbolAddress((void**)&pk, g_k);
    cudaGetSymbolAddress((void**)&pv, g_v);
    __half *hf, *af, *qh, *kh, *vh, *oh;
    __half *fqh, *fql, *fkh, *fkl, *fvh;
    cudaGetSymbolAddress((void**)&hf, g_hid_f16);
    cudaGetSymbolAddress((void**)&af, g_at_f16);
    cudaGetSymbolAddress((void**)&qh, g_wq_h);
    cudaGetSymbolAddress((void**)&kh, g_wk_h);
    cudaGetSymbolAddress((void**)&vh, g_wv_h);
    cudaGetSymbolAddress((void**)&oh, g_wo_h);
    cudaGetSymbolAddress((void**)&fqh, g_qh);   cudaGetSymbolAddress((void**)&fql, g_ql);
    cudaGetSymbolAddress((void**)&fkh, g_kh);   cudaGetSymbolAddress((void**)&fkl, g_kl);
    cudaGetSymbolAddress((void**)&fvh, g_vth);

    prep_all<<<(NPREP4 + 255) / 256, 256>>>(hid, Wq, Wk, Wv, Wo, pos);

    cudaFuncSetAttribute(gemm_qkv, cudaFuncAttributeMaxDynamicSharedMemorySize, GK1_SMEM);
    cudaFuncSetAttribute(gemm_mma1, cudaFuncAttributeMaxDynamicSharedMemorySize, GK1_SMEM);

    gemm_qkv<<<dim3(48, MROWS/BM), 256, GK1_SMEM>>>(hf, qh, kh, vh, pq, pk, pv);

    rope_split_qk<<<(MROWS*(NH+NKV)*32 + 255)/256, 256>>>();
    split_vt<<<BB*NKV*32, 256>>>();

    cudaFuncSetAttribute(flash_mma, cudaFuncAttributeMaxDynamicSharedMemorySize, FL_SMEM);
    flash_mma<<<dim3(SS/128, NH, BB), 256, FL_SMEM>>>(fqh, fql, fkh, fkl, fvh, af);

    gemm_mma1<<<dim3(NH*HD/BN, MROWS/BM), 256, GK1_SMEM>>>(af, oh, out, MROWS, NH*HD, NH*HD);
}

// round 17
// speedup vs baseline: 1.1083x; 1.0049x over previous
#include <cuda_runtime.h>
#include <cuda_fp16.h>
#include <math.h>
#include <stdint.h>

#define BB 2
#define SS 2048
#define DMODEL 4096
#define NH 32
#define NKV 8
#define HD 128
#define MROWS (BB*SS)   // 4096
#define QSCALE 0.08838834764831845f

extern __shared__ char dyn_smem[];

// ---------------- scratch (device globals; no allocation allowed) ----------
__device__ float g_v[(size_t)MROWS * NKV * HD];
__device__ float g_cos[MROWS * (HD/2)];
__device__ float g_sin[MROWS * (HD/2)];

// fp16 operands (weights hi only)
__device__ __half g_hid_f16[(size_t)MROWS * DMODEL];
__device__ __half g_at_f16[(size_t)MROWS * NH*HD];
__device__ __half g_wq_h[(size_t)NH*HD * DMODEL];
__device__ __half g_wk_h[(size_t)NKV*HD * DMODEL];
__device__ __half g_wv_h[(size_t)NKV*HD * DMODEL];
__device__ __half g_wo_h[(size_t)NH*HD * NH*HD];

// fp16 attention operands (post-rope, split)
__device__ __half g_qh[(size_t)MROWS * NH * HD];
__device__ __half g_ql[(size_t)MROWS * NH * HD];
__device__ __half g_kh[(size_t)MROWS * NKV * HD];
__device__ __half g_kl[(size_t)MROWS * NKV * HD];
__device__ __half g_vth[(size_t)BB * NKV * HD * SS];  // [b][kvh][d][s]

// ---------------- PTX helpers (sm_80+ base-target safe) ---------------------
__device__ __forceinline__ uint32_t smem_u32(const void* p) {
    uint32_t a;
    asm("{ .reg .u64 t; cvta.to.shared.u64 t, %1; cvt.u32.u64 %0, t; }" : "=r"(a) : "l"(p));
    return a;
}
__device__ __forceinline__ void cp16(uint32_t dst, const void* src) {
    asm volatile("cp.async.cg.shared.global [%0], [%1], 16;\n" :: "r"(dst), "l"(src));
}
__device__ __forceinline__ void cp_commit() { asm volatile("cp.async.commit_group;\n" ::: "memory"); }

__device__ __forceinline__ void ldm_x4(uint32_t* r, uint32_t addr) {
    asm volatile("ldmatrix.sync.aligned.m8n8.x4.shared.b16 {%0,%1,%2,%3}, [%4];"
        : "=r"(r[0]), "=r"(r[1]), "=r"(r[2]), "=r"(r[3]) : "r"(addr));
}
__device__ __forceinline__ void mma16816(float* d, const uint32_t* a, const uint32_t* b) {
    asm volatile("mma.sync.aligned.m16n8k16.row.col.f32.f16.f16.f32 "
        "{%0,%1,%2,%3}, {%4,%5,%6,%7}, {%8,%9}, {%0,%1,%2,%3};"
        : "+f"(d[0]), "+f"(d[1]), "+f"(d[2]), "+f"(d[3])
        : "r"(a[0]), "r"(a[1]), "r"(a[2]), "r"(a[3]), "r"(b[0]), "r"(b[1]));
}

// ---------------- fused prep (vectorized x4): fp32 -> fp16 + rope table ------
#define NW1 (NH*HD*DMODEL)
#define NW2 (NKV*HD*DMODEL)
#define NHID (MROWS*DMODEL)
#define NTAB (MROWS*64)
#define V_HID (NHID/4)
#define V_W1  (NW1/4)
#define V_W2  (NW2/4)
#define V_TAB (NTAB/4)
#define NPREP4 (V_HID + 2*V_W1 + 2*V_W2 + V_TAB)

__device__ __forceinline__ void cvt4(const float* __restrict__ src,
                                     __half* __restrict__ dst, int j4) {
    float4 f = ((const float4*)src)[j4];
    __half2 h0 = __floats2half2_rn(f.x, f.y);
    __half2 h1 = __floats2half2_rn(f.z, f.w);
    ((__half2*)dst)[j4 * 2 + 0] = h0;
    ((__half2*)dst)[j4 * 2 + 1] = h1;
}

__global__ void prep_all(const float* __restrict__ hid,
                         const float* __restrict__ Wq, const float* __restrict__ Wk,
                         const float* __restrict__ Wv, const float* __restrict__ Wo,
                         const int* __restrict__ pos) {
    int i = blockIdx.x * blockDim.x + threadIdx.x;
    if (i < V_HID) {
        cvt4(hid, g_hid_f16, i);
    } else if (i < V_HID + V_W1) {
        cvt4(Wq, g_wq_h, i - V_HID);
    } else if (i < V_HID + V_W1 + V_W2) {
        cvt4(Wk, g_wk_h, i - V_HID - V_W1);
    } else if (i < V_HID + V_W1 + 2*V_W2) {
        cvt4(Wv, g_wv_h, i - V_HID - V_W1 - V_W2);
    } else if (i < V_HID + 2*V_W1 + 2*V_W2) {
        cvt4(Wo, g_wo_h, i - V_HID - V_W1 - 2*V_W2);
    } else if (i < NPREP4) {
        int j4 = i - V_HID - 2*V_W1 - 2*V_W2;
        int j = j4 * 4;
        int row = j >> 6;
        int p = pos[row];
#pragma unroll
        for (int u = 0; u < 4; u++) {
            int fi = (j + u) & 63;
            double inv = exp(-(double)(2 * fi) / 128.0 * log(10000.0));
            double ang = (double)p * inv;
            float a = (float)fmod(ang, 6.283185307179586476925287);
            g_cos[j + u] = __cosf(a);
            g_sin[j + u] = __sinf(a);
        }
    }
}

// ---------------------------------------------------------------------------
// Single-term fp16 GEMM core (NT). CTA 128x128, 8 warps, BK=64, 3-stage,
// 2 CTAs/SM. Epilogue modes:
//   0: plain fp32 store to C
//   1: RoPE + fp16 hi/lo split -> (outh, outl), Q scaling
//   2: RoPE + fp16 hi/lo split -> (outh, outl), no scaling (K)
// Modes 1/2 bounce the acc tile through smem (stage buffers are dead).
// ---------------------------------------------------------------------------
#define BM 128
#define BN 128
#define ST1_BYTES 32768
#define GK1_SMEM (3*ST1_BYTES + 128)

__device__ __forceinline__ void gemm1_core(
    const __half* __restrict__ A, const __half* __restrict__ B,
    float* __restrict__ C, int bm, int bn, int N, int K,
    int mode, __half* __restrict__ outh, __half* __restrict__ outl, int headN) {
    uint32_t sm0 = (smem_u32(dyn_smem) + 127) & ~127u;

    int t = threadIdx.x;
    int wid = t >> 5, lane = t & 31;
    int wm = (wid >> 2) * 64;
    int wn = (wid & 3) * 32;

    float acc[4][4][4];
#pragma unroll
    for (int a = 0; a < 4; a++)
#pragma unroll
        for (int b = 0; b < 4; b++)
#pragma unroll
            for (int c = 0; c < 4; c++) acc[a][b][c] = 0.f;

    auto load_stage = [&](int s, int ck) {
        int k0 = ck * 64;
        uint32_t sb = sm0 + s * ST1_BYTES;
#pragma unroll
        for (int i = 0; i < 4; i++) {
            int idx = i * 256 + t;
            int r = idx >> 3, c = idx & 7;
            cp16(sb + r * 128 + ((c ^ (r & 7)) * 16),
                 A + (size_t)(bm + r) * K + k0 + c * 8);
        }
        uint32_t sbB = sb + 16384;
#pragma unroll
        for (int i = 0; i < 4; i++) {
            int idx = i * 256 + t;
            int r = idx >> 3, c = idx & 7;
            cp16(sbB + r * 128 + ((c ^ (r & 7)) * 16),
                 B + (size_t)(bn + r) * K + k0 + c * 8);
        }
        cp_commit();
    };

    const int NCH = K >> 6;
    load_stage(0, 0);
    load_stage(1, 1);

    int laneR = lane & 15, laneH = lane >> 4;
    uint32_t aOff[4], bOff[2];
#pragma unroll
    for (int mi = 0; mi < 4; mi++) {
        int r = wm + mi * 16 + laneR;
        aOff[mi] = sm0 + r * 128 + ((laneH ^ (r & 7)) * 16);
    }
#pragma unroll
    for (int nb = 0; nb < 2; nb++) {
        int r = wn + nb * 16 + laneR;
        bOff[nb] = sm0 + 16384 + r * 128 + ((laneH ^ (r & 7)) * 16);
    }

    for (int ch = 0; ch < NCH; ch++) {
        if (ch + 2 < NCH) {
            load_stage((ch + 2) % 3, ch + 2);
            asm volatile("cp.async.wait_group 2;\n" ::: "memory");
        } else if (ch + 1 < NCH) {
            asm volatile("cp.async.wait_group 1;\n" ::: "memory");
        } else {
            asm volatile("cp.async.wait_group 0;\n" ::: "memory");
        }
        __syncthreads();

        uint32_t soff = (uint32_t)(ch % 3) * ST1_BYTES;
#pragma unroll
        for (int kk = 0; kk < 4; kk++) {
            uint32_t kx = kk * 32;
            uint32_t ah[4][4];
#pragma unroll
            for (int mi = 0; mi < 4; mi++)
                ldm_x4(ah[mi], (aOff[mi] + soff) ^ kx);
#pragma unroll
            for (int nb = 0; nb < 2; nb++) {
                uint32_t bh[4];
                ldm_x4(bh, (bOff[nb] + soff) ^ kx);
#pragma unroll
                for (int mi = 0; mi < 4; mi++)
#pragma unroll
                    for (int sub = 0; sub < 2; sub++) {
                        int ni = nb * 2 + sub;
                        uint32_t fh[2] = { bh[sub], bh[2 + sub] };
                        mma16816(acc[mi][ni], ah[mi], fh);
                    }
            }
        }
        __syncthreads();
    }

    int row = lane >> 2;
    int col = (lane & 3) * 2;

    if (mode == 0) {
#pragma unroll
        for (int mi = 0; mi < 4; mi++)
#pragma unroll
            for (int ni = 0; ni < 4; ni++) {
                float* c0 = C + (size_t)(bm + wm + mi * 16 + row) * N + bn + wn + ni * 8 + col;
                c0[0] = acc[mi][ni][0];
                c0[1] = acc[mi][ni][1];
                float* c1 = c0 + 8 * (size_t)N;
                c1[0] = acc[mi][ni][2];
                c1[1] = acc[mi][ni][3];
            }
        return;
    }

    // --- RoPE + split epilogue: bounce acc through smem (stride 130 floats) --
    float* sf = (float*)dyn_smem;
#pragma unroll
    for (int mi = 0; mi < 4; mi++)
#pragma unroll
        for (int ni = 0; ni < 4; ni++) {
            int r0 = wm + mi * 16 + row;
            int c0 = wn + ni * 8 + col;
            sf[r0 * 130 + c0]     = acc[mi][ni][0];
            sf[r0 * 130 + c0 + 1] = acc[mi][ni][1];
            sf[(r0 + 8) * 130 + c0]     = acc[mi][ni][2];
            sf[(r0 + 8) * 130 + c0 + 1] = acc[mi][ni][3];
        }
    __syncthreads();

    const bool isQ = (mode == 1);
    const int head = bn >> 7;                  // 128 cols == one head
#pragma unroll
    for (int it = 0; it < 16; it++) {
        int j = it * 256 + t;                  // 0..4095
        int r = j >> 5;
        int i = (j & 31) * 2;
        float x1a = sf[r * 130 + i];
        float x1b = sf[r * 130 + i + 1];
        float x2a = sf[r * 130 + i + 64];
        float x2b = sf[r * 130 + i + 65];
        int gr = bm + r;
        float2 cc = *(const float2*)&g_cos[gr * 64 + i];
        float2 sn = *(const float2*)&g_sin[gr * 64 + i];
        float y1a = x1a * cc.x - x2a * sn.x;
        float y1b = x1b * cc.y - x2b * sn.y;
        float y2a = x2a * cc.x + x1a * sn.x;
        float y2b = x2b * cc.y + x1b * sn.y;
        if (isQ) { y1a *= QSCALE; y1b *= QSCALE; y2a *= QSCALE; y2b *= QSCALE; }
        __half2 h1 = __floats2half2_rn(y1a, y1b);
        __half2 h2 = __floats2half2_rn(y2a, y2b);
        size_t o = (size_t)gr * (size_t)headN + (size_t)head * HD;
        *(__half2*)&outh[o + i]      = h1;
        *(__half2*)&outh[o + i + 64] = h2;
        *(__half2*)&outl[o + i]      = __floats2half2_rn(y1a - __low2float(h1), y1b - __high2float(h1));
        *(__half2*)&outl[o + i + 64] = __floats2half2_rn(y2a - __low2float(h2), y2b - __high2float(h2));
    }
}

// fused QKV: 48 N-tiles (32 Q rope, 8 K rope, 8 V plain), one launch
__global__ __launch_bounds__(256, 2)
void gemm_qkv(const __half* __restrict__ A,
              const __half* __restrict__ Wqh, const __half* __restrict__ Wkh,
              const __half* __restrict__ Wvh,
              float* __restrict__ pv,
              __half* __restrict__ qh, __half* __restrict__ ql,
              __half* __restrict__ kh, __half* __restrict__ kl) {
    int tx = blockIdx.x;
    int bm = blockIdx.y * BM;
    if (tx < 32) {
        gemm1_core(A, Wqh, nullptr, bm, tx * 128, NH*HD, DMODEL, 1, qh, ql, NH*HD);
    } else if (tx < 40) {
        gemm1_core(A, Wkh, nullptr, bm, (tx - 32) * 128, NKV*HD, DMODEL, 2, kh, kl, NKV*HD);
    } else {
        gemm1_core(A, Wvh, pv, bm, (tx - 40) * 128, NKV*HD, DMODEL, 0, nullptr, nullptr, 0);
    }
}

__global__ __launch_bounds__(256, 2)
void gemm_mma1(const __half* __restrict__ A, const __half* __restrict__ B,
               float* __restrict__ C, int M, int N, int K) {
    gemm1_core(A, B, C, blockIdx.y * BM, blockIdx.x * BN, N, K, 0, nullptr, nullptr, 0);
}

// ---------------- V transpose: g_v -> Vt[b][kvh][d][s] fp16 (hi only) --------
__global__ __launch_bounds__(256) void split_vt() {
    __shared__ float sv[64][129];
    int blk = blockIdx.x;
    int st  = blk & 31;
    int kvh = (blk >> 5) & 7;
    int b   = blk >> 8;
    int tid = threadIdx.x;
#pragma unroll
    for (int it = 0; it < 32; it++) {
        int idx = it * 256 + tid;
        int r = idx >> 7, c = idx & 127;
        sv[r][c] = g_v[(size_t)(b * SS + st * 64 + r) * (NKV * HD) + kvh * HD + c];
    }
    __syncthreads();
    int d = tid >> 1, j = tid & 1;
    __half hbuf[32];
#pragma unroll
    for (int q = 0; q < 32; q++)
        hbuf[q] = __float2half(sv[j * 32 + q][d]);
    size_t base = ((size_t)(b * NKV + kvh) * HD + d) * SS + st * 64 + j * 32;
    uint4* dh = (uint4*)(g_vth + base);
#pragma unroll
    for (int q = 0; q < 4; q++)
        dh[q] = ((uint4*)hbuf)[q];
}

// ---------------------------------------------------------------------------
// HMMA flash attention: Br=128 (8 warps), Bc=64; QK 3-term, PV 2-term (P split).
// Double-buffered KV stages; prefetch kt+1 before computing kt.
// ---------------------------------------------------------------------------
#define SQH 0
#define SQL 32768
#define SKV 65536
#define KVSTG 49152
#define FL_SMEM (65536 + 2*KVSTG)   // 163840

__global__ __launch_bounds__(256) void flash_mma(
    const __half* __restrict__ Qh_g, const __half* __restrict__ Ql_g,
    const __half* __restrict__ Kh_g, const __half* __restrict__ Kl_g,
    const __half* __restrict__ Vth_g,
    __half* __restrict__ out) {
    uint32_t s0 = smem_u32(dyn_smem);

    int qt = blockIdx.x, h = blockIdx.y, b = blockIdx.z;
    int kvh = h >> 2;
    int t = threadIdx.x, wid = t >> 5, lane = t & 31;
    int laneR = lane & 15, laneH = lane >> 4;
    int wm = wid * 16;

#pragma unroll
    for (int i = 0; i < 8; i++) {
        int idx = i * 256 + t;
        int r = idx >> 4, c = idx & 15;
        uint32_t d = r * 256 + ((c ^ (r & 7)) * 16);
        size_t g = ((size_t)(b * SS + qt * 128 + r)) * (NH * HD) + h * HD + c * 8;
        cp16(s0 + SQH + d, Qh_g + g);
        cp16(s0 + SQL + d, Ql_g + g);
    }
    auto loadKV = [&](int kt, int st) {
        uint32_t base = s0 + SKV + (uint32_t)st * KVSTG;
#pragma unroll
        for (int i = 0; i < 4; i++) {
            int idx = i * 256 + t;
            int r = idx >> 4, c = idx & 15;
            uint32_t d = r * 256 + ((c ^ (r & 7)) * 16);
            size_t g = ((size_t)(b * SS + kt * 64 + r)) * (NKV * HD) + kvh * HD + c * 8;
            cp16(base + d, Kh_g + g);
        }
        uint32_t baseL = base + 16384;
#pragma unroll
        for (int i = 0; i < 4; i++) {
            int idx = i * 256 + t;
            int r = idx >> 4, c = idx & 15;
            uint32_t d = r * 256 + ((c ^ (r & 7)) * 16);
            size_t g = ((size_t)(b * SS + kt * 64 + r)) * (NKV * HD) + kvh * HD + c * 8;
            cp16(baseL + d, Kl_g + g);
        }
        uint32_t baseV = base + 32768;
#pragma unroll
        for (int i = 0; i < 4; i++) {
            int idx = i * 256 + t;
            int r = idx >> 3, c = idx & 7;
            uint32_t d = r * 128 + ((c ^ (r & 7)) * 16);
            size_t g = ((size_t)((b * NKV + kvh) * HD + r)) * SS + kt * 64 + c * 8;
            cp16(baseV + d, Vth_g + g);
        }
        cp_commit();
    };
    loadKV(0, 0);

    float o_[16][4];
#pragma unroll
    for (int n = 0; n < 16; n++)
#pragma unroll
        for (int c = 0; c < 4; c++) o_[n][c] = 0.f;
    float m0 = -1e30f, m1 = -1e30f, l0 = 0.f, l1 = 0.f;
    int r0 = lane >> 2;
    int qrow0 = qt * 128 + wm + r0;
    int qrow1 = qrow0 + 8;
    const int KTMAX = 2 * qt + 1;

    for (int kt = 0; kt <= KTMAX; kt++) {
        if (kt < KTMAX) {
            loadKV(kt + 1, (kt + 1) & 1);
            asm volatile("cp.async.wait_group 1;\n" ::: "memory");
        } else {
            asm volatile("cp.async.wait_group 0;\n" ::: "memory");
        }
        __syncthreads();

        uint32_t kvb  = s0 + SKV + (uint32_t)(kt & 1) * KVSTG;
        uint32_t kvbl = kvb + 16384;
        uint32_t kvbv = kvb + 32768;

        float s[8][4];
#pragma unroll
        for (int j = 0; j < 8; j++)
#pragma unroll
            for (int c = 0; c < 4; c++) s[j][c] = 0.f;

#pragma unroll
        for (int kk = 0; kk < 8; kk++) {
            uint32_t qa[4], qb[4];
            {
                int r = wm + laneR;
                uint32_t ph = (uint32_t)(((kk * 2 + laneH) ^ (r & 7)) * 16);
                ldm_x4(qa, s0 + SQH + r * 256 + ph);
                ldm_x4(qb, s0 + SQL + r * 256 + ph);
            }
#pragma unroll
            for (int jj = 0; jj < 4; jj++) {
                uint32_t kh_[4], kl_[4];
                int r = jj * 16 + laneR;
                uint32_t ph = (uint32_t)(((kk * 2 + laneH) ^ (r & 7)) * 16);
                ldm_x4(kh_, kvb  + r * 256 + ph);
                ldm_x4(kl_, kvbl + r * 256 + ph);
#pragma unroll
                for (int sub = 0; sub < 2; sub++) {
                    int j = jj * 2 + sub;
                    uint32_t fh[2] = { kh_[sub], kh_[2 + sub] };
                    uint32_t fl[2] = { kl_[sub], kl_[2 + sub] };
                    mma16816(s[j], qa, fh);
                    mma16816(s[j], qa, fl);
                    mma16816(s[j], qb, fh);
                }
            }
        }

        if (kt * 64 + 63 > qrow0) {
#pragma unroll
            for (int j = 0; j < 8; j++) {
                int cb = kt * 64 + j * 8 + (lane & 3) * 2;
                if (cb     > qrow0) s[j][0] = -1e30f;
                if (cb + 1 > qrow0) s[j][1] = -1e30f;
                if (cb     > qrow1) s[j][2] = -1e30f;
                if (cb + 1 > qrow1) s[j][3] = -1e30f;
            }
        }

        float rm0 = -1e30f, rm1 = -1e30f;
#pragma unroll
        for (int j = 0; j < 8; j++) {
            rm0 = fmaxf(rm0, fmaxf(s[j][0], s[j][1]));
            rm1 = fmaxf(rm1, fmaxf(s[j][2], s[j][3]));
        }
        rm0 = fmaxf(rm0, __shfl_xor_sync(0xffffffffu, rm0, 1));
        rm0 = fmaxf(rm0, __shfl_xor_sync(0xffffffffu, rm0, 2));
        rm1 = fmaxf(rm1, __shfl_xor_sync(0xffffffffu, rm1, 1));
        rm1 = fmaxf(rm1, __shfl_xor_sync(0xffffffffu, rm1, 2));
        float mn0 = fmaxf(m0, rm0), mn1 = fmaxf(m1, rm1);
        float a0 = __expf(m0 - mn0), a1 = __expf(m1 - mn1);
        l0 *= a0; l1 *= a1;
#pragma unroll
        for (int n = 0; n < 16; n++) {
            o_[n][0] *= a0; o_[n][1] *= a0;
            o_[n][2] *= a1; o_[n][3] *= a1;
        }
        m0 = mn0; m1 = mn1;

        uint32_t ph0[8], ph1[8], pl0[8], pl1[8];
        float sum0 = 0.f, sum1 = 0.f;
#pragma unroll
        for (int j = 0; j < 8; j++) {
            float e0 = __expf(s[j][0] - mn0), e1 = __expf(s[j][1] - mn0);
            float e2 = __expf(s[j][2] - mn1), e3 = __expf(s[j][3] - mn1);
            sum0 += e0 + e1; sum1 += e2 + e3;
            __half2 hh0 = __floats2half2_rn(e0, e1);
            __half2 hh1 = __floats2half2_rn(e2, e3);
            ph0[j] = *(uint32_t*)&hh0;
            ph1[j] = *(uint32_t*)&hh1;
            __half2 dd0 = __floats2half2_rn(e0 - __low2float(hh0), e1 - __high2float(hh0));
            __half2 dd1 = __floats2half2_rn(e2 - __low2float(hh1), e3 - __high2float(hh1));
            pl0[j] = *(uint32_t*)&dd0;
            pl1[j] = *(uint32_t*)&dd1;
        }
        sum0 += __shfl_xor_sync(0xffffffffu, sum0, 1);
        sum0 += __shfl_xor_sync(0xffffffffu, sum0, 2);
        sum1 += __shfl_xor_sync(0xffffffffu, sum1, 1);
        sum1 += __shfl_xor_sync(0xffffffffu, sum1, 2);
        l0 += sum0; l1 += sum1;

#pragma unroll
        for (int tt = 0; tt < 4; tt++) {
            uint32_t pa[4] = { ph0[2*tt], ph1[2*tt], ph0[2*tt+1], ph1[2*tt+1] };
            uint32_t pb[4] = { pl0[2*tt], pl1[2*tt], pl0[2*tt+1], pl1[2*tt+1] };
#pragma unroll
            for (int dg = 0; dg < 8; dg++) {
                uint32_t vh_[4];
                int r = dg * 16 + laneR;
                uint32_t ph = (uint32_t)(((tt * 2 + laneH) ^ (r & 7)) * 16);
                ldm_x4(vh_, kvbv + r * 128 + ph);
#pragma unroll
                for (int sub = 0; sub < 2; sub++) {
                    int n = dg * 2 + sub;
                    uint32_t fh[2] = { vh_[sub], vh_[2 + sub] };
                    mma16816(o_[n], pa, fh);
                    mma16816(o_[n], pb, fh);
                }
            }
        }

        __syncthreads();
    }

    float il0 = 1.f / l0, il1 = 1.f / l1;
    size_t ob0 = (size_t)(b * SS + qrow0) * (NH * HD) + h * HD + (lane & 3) * 2;
    size_t ob1 = (size_t)(b * SS + qrow1) * (NH * HD) + h * HD + (lane & 3) * 2;
#pragma unroll
    for (int n = 0; n < 16; n++) {
        __half2 w0 = __floats2half2_rn(o_[n][0] * il0, o_[n][1] * il0);
        __half2 w1 = __floats2half2_rn(o_[n][2] * il1, o_[n][3] * il1);
        *(__half2*)(out + ob0 + n * 8) = w0;
        *(__half2*)(out + ob1 + n * 8) = w1;
    }
}

// ---------------------------------------------------------------------------
extern "C" void kernel_launch(void* const* d_in, const int* in_sizes, int n_in,
                              void* d_out, int out_size) {
    const float* hid = (const float*)d_in[0];
    const int*   pos = (const int*)d_in[1];
    const float* Wq  = (const float*)d_in[2];
    const float* Wk  = (const float*)d_in[3];
    const float* Wv  = (const float*)d_in[4];
    const float* Wo  = (const float*)d_in[5];
    float* out = (float*)d_out;

    float* pv;
    cudaGetSymbolAddress((void**)&pv, g_v);
    __half *hf, *af, *qh, *kh, *vh, *oh;
    __half *fqh, *fql, *fkh, *fkl, *fvh;
    cudaGetSymbolAddress((void**)&hf, g_hid_f16);
    cudaGetSymbolAddress((void**)&af, g_at_f16);
    cudaGetSymbolAddress((void**)&qh, g_wq_h);
    cudaGetSymbolAddress((void**)&kh, g_wk_h);
    cudaGetSymbolAddress((void**)&vh, g_wv_h);
    cudaGetSymbolAddress((void**)&oh, g_wo_h);
    cudaGetSymbolAddress((void**)&fqh, g_qh);   cudaGetSymbolAddress((void**)&fql, g_ql);
    cudaGetSymbolAddress((void**)&fkh, g_kh);   cudaGetSymbolAddress((void**)&fkl, g_kl);
    cudaGetSymbolAddress((void**)&fvh, g_vth);

    prep_all<<<(NPREP4 + 255) / 256, 256>>>(hid, Wq, Wk, Wv, Wo, pos);

    cudaFuncSetAttribute(gemm_qkv, cudaFuncAttributeMaxDynamicSharedMemorySize, GK1_SMEM);
    cudaFuncSetAttribute(gemm_mma1, cudaFuncAttributeMaxDynamicSharedMemorySize, GK1_SMEM);

    gemm_qkv<<<dim3(48, MROWS/BM), 256, GK1_SMEM>>>(hf, qh, kh, vh, pv, fqh, fql, fkh, fkl);

    split_vt<<<BB*NKV*32, 256>>>();

    cudaFuncSetAttribute(flash_mma, cudaFuncAttributeMaxDynamicSharedMemorySize, FL_SMEM);
    flash_mma<<<dim3(SS/128, NH, BB), 256, FL_SMEM>>>(fqh, fql, fkh, fkl, fvh, af);

    gemm_mma1<<<dim3(NH*HD/BN, MROWS/BM), 256, GK1_SMEM>>>(af, oh, out, MROWS, NH*HD, NH*HD);
}